// round 1
// baseline (speedup 1.0000x reference)
#include <cuda_runtime.h>

#define BB 32
#define LL 512
#define DIN 768
#define HH 16
#define DHH 48
#define DOUTC 768
#define M_TOT (BB*LL)
#define NEGC 1e12f
#define SCALEC 0.14433756729740643f   /* 1/sqrt(48) */

// Scratch (static device globals — allowed; no runtime allocation)
__device__ float g_q[(size_t)M_TOT * DOUTC];
__device__ float g_k[(size_t)M_TOT * DOUTC];
__device__ float g_v[(size_t)M_TOT * DOUTC];
__device__ float g_a[(size_t)BB * HH * LL * LL];   // 512 MB attention matrix

// ---------------------------------------------------------------------------
// Kernel 1: projection SGEMM  Y[16384,768] = X[16384,768] @ W[768,768]
// 128x128 tile, 256 threads, 8x8 per thread, K-chunk 8
// ---------------------------------------------------------------------------
__global__ __launch_bounds__(256) void proj_gemm(const float* __restrict__ X,
                                                 const float* __restrict__ W,
                                                 float* __restrict__ Y) {
    __shared__ float Ast[8][128];   // A stored transposed: Ast[k][m]
    __shared__ float Bs[8][128];

    const int t  = threadIdx.x;
    const int tx = t & 15;          // 0..15 -> 8 cols each
    const int ty = t >> 4;          // 0..15 -> 8 rows each
    const int mBase = blockIdx.y * 128;
    const int nBase = blockIdx.x * 128;

    float acc[8][8];
    #pragma unroll
    for (int i = 0; i < 8; i++)
        #pragma unroll
        for (int j = 0; j < 8; j++) acc[i][j] = 0.0f;

    const int arow  = t >> 1;          // 0..127
    const int ahalf = (t & 1) * 4;     // 0 or 4
    const int brow  = t >> 5;          // 0..7
    const int bvec  = (t & 31) * 4;    // 0..124

    const float* Xp = X + (size_t)(mBase + arow) * DIN + ahalf;
    const float* Wp = W + (size_t)brow * DOUTC + nBase + bvec;

    for (int kk = 0; kk < DIN; kk += 8) {
        float4 av = *(const float4*)(Xp + kk);
        float4 bv = *(const float4*)(Wp + (size_t)kk * DOUTC);
        __syncthreads();
        Ast[ahalf + 0][arow] = av.x;
        Ast[ahalf + 1][arow] = av.y;
        Ast[ahalf + 2][arow] = av.z;
        Ast[ahalf + 3][arow] = av.w;
        *(float4*)&Bs[brow][bvec] = bv;
        __syncthreads();
        #pragma unroll
        for (int k = 0; k < 8; k++) {
            float a[8], b[8];
            *(float4*)(&a[0]) = *(const float4*)(&Ast[k][ty * 8]);
            *(float4*)(&a[4]) = *(const float4*)(&Ast[k][ty * 8 + 4]);
            *(float4*)(&b[0]) = *(const float4*)(&Bs[k][tx * 8]);
            *(float4*)(&b[4]) = *(const float4*)(&Bs[k][tx * 8 + 4]);
            #pragma unroll
            for (int i = 0; i < 8; i++)
                #pragma unroll
                for (int j = 0; j < 8; j++)
                    acc[i][j] += a[i] * b[j];
        }
    }

    #pragma unroll
    for (int i = 0; i < 8; i++) {
        const size_t m = (size_t)(mBase + ty * 8 + i);
        float4* o = (float4*)(Y + m * DOUTC + nBase + tx * 8);
        o[0] = make_float4(acc[i][0], acc[i][1], acc[i][2], acc[i][3]);
        o[1] = make_float4(acc[i][4], acc[i][5], acc[i][6], acc[i][7]);
    }
}

// ---------------------------------------------------------------------------
// Kernel 2: scores + masks + softmax -> A scratch
// grid (16 q-tiles, H, B); block 256 threads; 32 q-rows x 512 k per block.
// thread: qr = t/8 (q row), sub = t%8; owns 64 k-columns in registers.
// ---------------------------------------------------------------------------
__global__ __launch_bounds__(256) void attn_scores(const long long dummy,
                                                   const int* __restrict__ Vlen) {
    const int b  = blockIdx.z;
    const int h  = blockIdx.y;
    const int qt = blockIdx.x;
    const int t   = threadIdx.x;
    const int sub = t & 7;
    const int qr  = t >> 3;
    const int qglob = qt * 32 + qr;

    __shared__ float qs[32][49];
    __shared__ float ks[64][49];

    for (int i = t; i < 32 * 48; i += 256) {
        const int r = i / 48, c = i % 48;
        qs[r][c] = g_q[(size_t)(b * LL + qt * 32 + r) * DOUTC + h * DHH + c];
    }

    const int vlen = Vlen[b];
    float s[64];
    float mx = -__int_as_float(0x7f800000) * 0.0f - 1e30f;  // large negative
    mx = -3.4e38f;

    for (int kt = 0; kt < 8; kt++) {
        __syncthreads();
        for (int i = t; i < 64 * 48; i += 256) {
            const int r = i / 48, c = i % 48;
            ks[r][c] = g_k[(size_t)(b * LL + kt * 64 + r) * DOUTC + h * DHH + c];
        }
        __syncthreads();
        #pragma unroll
        for (int j = 0; j < 8; j++) {
            const int kc = j * 8 + sub;
            const int kg = kt * 64 + kc;
            float acc = 0.0f;
            #pragma unroll
            for (int d = 0; d < 48; d++) acc += qs[qr][d] * ks[kc][d];
            acc *= SCALEC;
            if (kg >= vlen) acc -= NEGC;     // key-length mask
            if (kg > qglob) acc -= NEGC;     // causal mask (both may apply)
            s[kt * 8 + j] = acc;
            mx = fmaxf(mx, acc);
        }
    }

    // reduce max over the 8 threads of this q-row (consecutive lanes)
    #pragma unroll
    for (int o = 1; o < 8; o <<= 1)
        mx = fmaxf(mx, __shfl_xor_sync(0xffffffffu, mx, o));

    float sum = 0.0f;
    #pragma unroll
    for (int i = 0; i < 64; i++) { s[i] = __expf(s[i] - mx); sum += s[i]; }
    #pragma unroll
    for (int o = 1; o < 8; o <<= 1)
        sum += __shfl_xor_sync(0xffffffffu, sum, o);
    const float inv = 1.0f / sum;

    const size_t base = (((size_t)(b * HH + h)) * LL + qglob) * LL;
    #pragma unroll
    for (int kt = 0; kt < 8; kt++)
        #pragma unroll
        for (int j = 0; j < 8; j++)
            g_a[base + kt * 64 + j * 8 + sub] = s[kt * 8 + j] * inv;
}

// ---------------------------------------------------------------------------
// Kernel 3: O[b,k,h,d] = sum_q A[b,h,q,k] * V[b,h,q,d], then * (k < Q_len[b])
// grid (4 k-tiles of 128, H, B); block 256: tx=t%8 (6 d each), ty=t/8 (4 k each)
// ---------------------------------------------------------------------------
__global__ __launch_bounds__(256) void attn_av(const int* __restrict__ Qlen,
                                               float* __restrict__ O) {
    const int b = blockIdx.z, h = blockIdx.y, ktile = blockIdx.x;
    const int t  = threadIdx.x;
    const int tx = t & 7;    // d group of 6
    const int ty = t >> 3;   // k group of 4
    const int kBase = ktile * 128;

    __shared__ float As[64][128];
    __shared__ float Vs[64][49];

    float acc[4][6];
    #pragma unroll
    for (int i = 0; i < 4; i++)
        #pragma unroll
        for (int j = 0; j < 6; j++) acc[i][j] = 0.0f;

    const size_t abase = (((size_t)(b * HH + h)) * LL) * LL + kBase;

    for (int qc = 0; qc < 8; qc++) {
        __syncthreads();
        for (int i = t; i < 64 * 32; i += 256) {   // 2048 float4 loads
            const int r = i >> 5;
            const int vec = (i & 31) * 4;
            *(float4*)&As[r][vec] =
                *(const float4*)&g_a[abase + (size_t)(qc * 64 + r) * LL + vec];
        }
        for (int i = t; i < 64 * 48; i += 256) {
            const int r = i / 48, c = i % 48;
            Vs[r][c] = g_v[(size_t)(b * LL + qc * 64 + r) * DOUTC + h * DHH + c];
        }
        __syncthreads();
        #pragma unroll 4
        for (int q = 0; q < 64; q++) {
            float a[4];
            *(float4*)a = *(const float4*)&As[q][ty * 4];
            #pragma unroll
            for (int j = 0; j < 6; j++) {
                const float vv = Vs[q][tx * 6 + j];
                #pragma unroll
                for (int i = 0; i < 4; i++) acc[i][j] += a[i] * vv;
            }
        }
    }

    const int qlen = Qlen[b];
    #pragma unroll
    for (int i = 0; i < 4; i++) {
        const int kg = kBase + ty * 4 + i;
        const float m = (kg < qlen) ? 1.0f : 0.0f;
        float* op = O + (size_t)(b * LL + kg) * DOUTC + h * DHH + tx * 6;
        #pragma unroll
        for (int j = 0; j < 6; j++) op[j] = acc[i][j] * m;
    }
}

// ---------------------------------------------------------------------------
extern "C" void kernel_launch(void* const* d_in, const int* in_sizes, int n_in,
                              void* d_out, int out_size) {
    const float* Qseq = (const float*)d_in[0];
    const float* Kseq = (const float*)d_in[1];
    const float* Vseq = (const float*)d_in[2];
    const float* WQ   = (const float*)d_in[3];
    const float* WK   = (const float*)d_in[4];
    const float* WV   = (const float*)d_in[5];
    const int*   Qlen = (const int*)d_in[6];
    const int*   Vlen = (const int*)d_in[7];

    float *gq, *gk, *gv;
    cudaGetSymbolAddress((void**)&gq, g_q);
    cudaGetSymbolAddress((void**)&gk, g_k);
    cudaGetSymbolAddress((void**)&gv, g_v);

    dim3 gproj(6, 128);
    proj_gemm<<<gproj, 256>>>(Qseq, WQ, gq);
    proj_gemm<<<gproj, 256>>>(Kseq, WK, gk);
    proj_gemm<<<gproj, 256>>>(Vseq, WV, gv);

    attn_scores<<<dim3(16, HH, BB), 256>>>(0LL, Vlen);
    attn_av<<<dim3(4, HH, BB), 256>>>(Qlen, (float*)d_out);
}

// round 2
// speedup vs baseline: 1.4171x; 1.4171x over previous
#include <cuda_runtime.h>

#define BB 32
#define LL 512
#define DIN 768
#define HH 16
#define DHH 48
#define DOUTC 768
#define M_TOT (BB*LL)
#define NEGC 1e12f
#define SCALEC 0.14433756729740643f   /* 1/sqrt(48) */

// Scratch (static device globals — allowed; no runtime allocation)
__device__ float g_q[(size_t)M_TOT * DOUTC];
__device__ float g_k[(size_t)M_TOT * DOUTC];
__device__ float g_v[(size_t)M_TOT * DOUTC];
__device__ float g_a[(size_t)BB * HH * LL * LL];   // 512 MB attention matrix

__device__ __forceinline__ unsigned f2tf32(float x) {
    unsigned r;
    asm("cvt.rna.tf32.f32 %0, %1;" : "=r"(r) : "f"(x));
    return r;
}

__device__ __forceinline__ void mma_tf32(float* c, const unsigned* a, const unsigned* b) {
    asm volatile(
        "mma.sync.aligned.m16n8k8.row.col.f32.tf32.tf32.f32 "
        "{%0,%1,%2,%3}, {%4,%5,%6,%7}, {%8,%9}, {%0,%1,%2,%3};"
        : "+f"(c[0]), "+f"(c[1]), "+f"(c[2]), "+f"(c[3])
        : "r"(a[0]), "r"(a[1]), "r"(a[2]), "r"(a[3]), "r"(b[0]), "r"(b[1]));
}

// ---------------------------------------------------------------------------
// Kernel 1: TF32 tensor-core projection GEMM  Y[16384,768] = X @ W[768,768]
// 128x128 tile, BK=16, 8 warps (2x4), each warp 64x32 via m16n8k8 mma.
// ---------------------------------------------------------------------------
#define PADW 132
__global__ __launch_bounds__(256) void proj_gemm_tc(const float* __restrict__ X,
                                                    const float* __restrict__ W,
                                                    float* __restrict__ Y) {
    __shared__ unsigned As[16][PADW];   // As[k][m]
    __shared__ unsigned Bs[16][PADW];   // Bs[k][n]

    const int t = threadIdx.x;
    const int lane = t & 31;
    const int w = t >> 5;
    const int wm = w >> 2;        // 0..1  -> 64 rows
    const int wn = w & 3;         // 0..3  -> 32 cols
    const int g   = lane >> 2;    // groupID 0..7
    const int tig = lane & 3;     // thread-in-group 0..3

    const int mBase = blockIdx.y * 128;
    const int nBase = blockIdx.x * 128;
    const int m0 = wm * 64;
    const int n0 = wn * 32;

    float acc[4][4][4];
    #pragma unroll
    for (int i = 0; i < 4; i++)
        #pragma unroll
        for (int j = 0; j < 4; j++)
            #pragma unroll
            for (int c = 0; c < 4; c++) acc[i][j][c] = 0.0f;

    // global-load assignments (2 float4 each for A and B per chunk)
    const int arow0 = t >> 1;                 // via idx = t + i*256
    for (int kk = 0; kk < DIN; kk += 16) {
        __syncthreads();
        #pragma unroll
        for (int i = 0; i < 2; i++) {
            const int idx = t + i * 256;       // 0..511
            const int row = idx >> 2;          // 0..127
            const int kq  = (idx & 3) * 4;
            float4 v = *(const float4*)(X + (size_t)(mBase + row) * DIN + kk + kq);
            As[kq + 0][row] = f2tf32(v.x);
            As[kq + 1][row] = f2tf32(v.y);
            As[kq + 2][row] = f2tf32(v.z);
            As[kq + 3][row] = f2tf32(v.w);
        }
        #pragma unroll
        for (int i = 0; i < 2; i++) {
            const int idx = t + i * 256;       // 0..511
            const int krow = idx >> 5;         // 0..15
            const int nq   = (idx & 31) * 4;
            float4 v = *(const float4*)(W + (size_t)(kk + krow) * DOUTC + nBase + nq);
            Bs[krow][nq + 0] = f2tf32(v.x);
            Bs[krow][nq + 1] = f2tf32(v.y);
            Bs[krow][nq + 2] = f2tf32(v.z);
            Bs[krow][nq + 3] = f2tf32(v.w);
        }
        __syncthreads();

        #pragma unroll
        for (int ks = 0; ks < 2; ks++) {
            const int kb = ks * 8;
            unsigned a[4][4], b[4][2];
            #pragma unroll
            for (int i = 0; i < 4; i++) {
                a[i][0] = As[kb + tig    ][m0 + i * 16 + g];
                a[i][1] = As[kb + tig    ][m0 + i * 16 + g + 8];
                a[i][2] = As[kb + tig + 4][m0 + i * 16 + g];
                a[i][3] = As[kb + tig + 4][m0 + i * 16 + g + 8];
            }
            #pragma unroll
            for (int j = 0; j < 4; j++) {
                b[j][0] = Bs[kb + tig    ][n0 + j * 8 + g];
                b[j][1] = Bs[kb + tig + 4][n0 + j * 8 + g];
            }
            #pragma unroll
            for (int i = 0; i < 4; i++)
                #pragma unroll
                for (int j = 0; j < 4; j++)
                    mma_tf32(acc[i][j], a[i], b[j]);
        }
    }
    (void)arow0;

    // epilogue: c0/c1 at (row=g, col=tig*2, +1), c2/c3 at row=g+8
    #pragma unroll
    for (int i = 0; i < 4; i++) {
        const size_t r1 = (size_t)(mBase + m0 + i * 16 + g);
        const size_t r2 = r1 + 8;
        #pragma unroll
        for (int j = 0; j < 4; j++) {
            const int col = nBase + n0 + j * 8 + tig * 2;
            *(float2*)(Y + r1 * DOUTC + col) = make_float2(acc[i][j][0], acc[i][j][1]);
            *(float2*)(Y + r2 * DOUTC + col) = make_float2(acc[i][j][2], acc[i][j][3]);
        }
    }
}

// ---------------------------------------------------------------------------
// Kernel 2: scores + masks + softmax -> A scratch (unchanged from R1)
// ---------------------------------------------------------------------------
__global__ __launch_bounds__(256) void attn_scores(const long long dummy,
                                                   const int* __restrict__ Vlen) {
    const int b  = blockIdx.z;
    const int h  = blockIdx.y;
    const int qt = blockIdx.x;
    const int t   = threadIdx.x;
    const int sub = t & 7;
    const int qr  = t >> 3;
    const int qglob = qt * 32 + qr;

    __shared__ float qs[32][49];
    __shared__ float ks[64][49];

    for (int i = t; i < 32 * 48; i += 256) {
        const int r = i / 48, c = i % 48;
        qs[r][c] = g_q[(size_t)(b * LL + qt * 32 + r) * DOUTC + h * DHH + c];
    }

    const int vlen = Vlen[b];
    float s[64];
    float mx = -3.4e38f;

    for (int kt = 0; kt < 8; kt++) {
        __syncthreads();
        for (int i = t; i < 64 * 48; i += 256) {
            const int r = i / 48, c = i % 48;
            ks[r][c] = g_k[(size_t)(b * LL + kt * 64 + r) * DOUTC + h * DHH + c];
        }
        __syncthreads();
        #pragma unroll
        for (int j = 0; j < 8; j++) {
            const int kc = j * 8 + sub;
            const int kg = kt * 64 + kc;
            float acc = 0.0f;
            #pragma unroll
            for (int d = 0; d < 48; d++) acc += qs[qr][d] * ks[kc][d];
            acc *= SCALEC;
            if (kg >= vlen) acc -= NEGC;     // key-length mask
            if (kg > qglob) acc -= NEGC;     // causal mask (both may apply)
            s[kt * 8 + j] = acc;
            mx = fmaxf(mx, acc);
        }
    }

    #pragma unroll
    for (int o = 1; o < 8; o <<= 1)
        mx = fmaxf(mx, __shfl_xor_sync(0xffffffffu, mx, o));

    float sum = 0.0f;
    #pragma unroll
    for (int i = 0; i < 64; i++) { s[i] = __expf(s[i] - mx); sum += s[i]; }
    #pragma unroll
    for (int o = 1; o < 8; o <<= 1)
        sum += __shfl_xor_sync(0xffffffffu, sum, o);
    const float inv = 1.0f / sum;

    const size_t base = (((size_t)(b * HH + h)) * LL + qglob) * LL;
    #pragma unroll
    for (int kt = 0; kt < 8; kt++)
        #pragma unroll
        for (int j = 0; j < 8; j++)
            g_a[base + kt * 64 + j * 8 + sub] = s[kt * 8 + j] * inv;
}

// ---------------------------------------------------------------------------
// Kernel 3: O[b,k,h,d] = sum_q A[b,h,q,k] * V[b,h,q,d], * (k < Q_len[b])
// (unchanged from R1)
// ---------------------------------------------------------------------------
__global__ __launch_bounds__(256) void attn_av(const int* __restrict__ Qlen,
                                               float* __restrict__ O) {
    const int b = blockIdx.z, h = blockIdx.y, ktile = blockIdx.x;
    const int t  = threadIdx.x;
    const int tx = t & 7;    // d group of 6
    const int ty = t >> 3;   // k group of 4
    const int kBase = ktile * 128;

    __shared__ float As[64][128];
    __shared__ float Vs[64][49];

    float acc[4][6];
    #pragma unroll
    for (int i = 0; i < 4; i++)
        #pragma unroll
        for (int j = 0; j < 6; j++) acc[i][j] = 0.0f;

    const size_t abase = (((size_t)(b * HH + h)) * LL) * LL + kBase;

    for (int qc = 0; qc < 8; qc++) {
        __syncthreads();
        for (int i = t; i < 64 * 32; i += 256) {
            const int r = i >> 5;
            const int vec = (i & 31) * 4;
            *(float4*)&As[r][vec] =
                *(const float4*)&g_a[abase + (size_t)(qc * 64 + r) * LL + vec];
        }
        for (int i = t; i < 64 * 48; i += 256) {
            const int r = i / 48, c = i % 48;
            Vs[r][c] = g_v[(size_t)(b * LL + qc * 64 + r) * DOUTC + h * DHH + c];
        }
        __syncthreads();
        #pragma unroll 4
        for (int q = 0; q < 64; q++) {
            float a[4];
            *(float4*)a = *(const float4*)&As[q][ty * 4];
            #pragma unroll
            for (int j = 0; j < 6; j++) {
                const float vv = Vs[q][tx * 6 + j];
                #pragma unroll
                for (int i = 0; i < 4; i++) acc[i][j] += a[i] * vv;
            }
        }
    }

    const int qlen = Qlen[b];
    #pragma unroll
    for (int i = 0; i < 4; i++) {
        const int kg = kBase + ty * 4 + i;
        const float m = (kg < qlen) ? 1.0f : 0.0f;
        float* op = O + (size_t)(b * LL + kg) * DOUTC + h * DHH + tx * 6;
        #pragma unroll
        for (int j = 0; j < 6; j++) op[j] = acc[i][j] * m;
    }
}

// ---------------------------------------------------------------------------
extern "C" void kernel_launch(void* const* d_in, const int* in_sizes, int n_in,
                              void* d_out, int out_size) {
    const float* Qseq = (const float*)d_in[0];
    const float* Kseq = (const float*)d_in[1];
    const float* Vseq = (const float*)d_in[2];
    const float* WQ   = (const float*)d_in[3];
    const float* WK   = (const float*)d_in[4];
    const float* WV   = (const float*)d_in[5];
    const int*   Qlen = (const int*)d_in[6];
    const int*   Vlen = (const int*)d_in[7];

    float *gq, *gk, *gv;
    cudaGetSymbolAddress((void**)&gq, g_q);
    cudaGetSymbolAddress((void**)&gk, g_k);
    cudaGetSymbolAddress((void**)&gv, g_v);

    dim3 gproj(6, 128);
    proj_gemm_tc<<<gproj, 256>>>(Qseq, WQ, gq);
    proj_gemm_tc<<<gproj, 256>>>(Kseq, WK, gk);
    proj_gemm_tc<<<gproj, 256>>>(Vseq, WV, gv);

    attn_scores<<<dim3(16, HH, BB), 256>>>(0LL, Vlen);
    attn_av<<<dim3(4, HH, BB), 256>>>(Qlen, (float*)d_out);
}

// round 3
// speedup vs baseline: 2.1377x; 1.5084x over previous
#include <cuda_runtime.h>

#define BB 32
#define LL 512
#define DIN 768
#define HH 16
#define DHH 48
#define DOUTC 768
#define M_TOT (BB*LL)
#define NEGC 1e12f
#define SCALEC 0.14433756729740643f   /* 1/sqrt(48) */

// Scratch (static device globals — allowed; no runtime allocation)
__device__ float g_q[(size_t)M_TOT * DOUTC];
__device__ float g_k[(size_t)M_TOT * DOUTC];
__device__ float g_v[(size_t)M_TOT * DOUTC];

__device__ __forceinline__ unsigned f2tf32(float x) {
    unsigned r;
    asm("cvt.rna.tf32.f32 %0, %1;" : "=r"(r) : "f"(x));
    return r;
}

__device__ __forceinline__ void mma_tf32(float* c, const unsigned* a, const unsigned* b) {
    asm volatile(
        "mma.sync.aligned.m16n8k8.row.col.f32.tf32.tf32.f32 "
        "{%0,%1,%2,%3}, {%4,%5,%6,%7}, {%8,%9}, {%0,%1,%2,%3};"
        : "+f"(c[0]), "+f"(c[1]), "+f"(c[2]), "+f"(c[3])
        : "r"(a[0]), "r"(a[1]), "r"(a[2]), "r"(a[3]), "r"(b[0]), "r"(b[1]));
}

// ---------------------------------------------------------------------------
// Kernel 1: TF32 tensor-core projection GEMM  Y[16384,768] = X @ W[768,768]
// (validated in R2)
// ---------------------------------------------------------------------------
#define PADW 132
__global__ __launch_bounds__(256) void proj_gemm_tc(const float* __restrict__ X,
                                                    const float* __restrict__ W,
                                                    float* __restrict__ Y) {
    __shared__ unsigned As[16][PADW];   // As[k][m]
    __shared__ unsigned Bs[16][PADW];   // Bs[k][n]

    const int t = threadIdx.x;
    const int lane = t & 31;
    const int w = t >> 5;
    const int wm = w >> 2;
    const int wn = w & 3;
    const int g   = lane >> 2;
    const int tig = lane & 3;

    const int mBase = blockIdx.y * 128;
    const int nBase = blockIdx.x * 128;
    const int m0 = wm * 64;
    const int n0 = wn * 32;

    float acc[4][4][4];
    #pragma unroll
    for (int i = 0; i < 4; i++)
        #pragma unroll
        for (int j = 0; j < 4; j++)
            #pragma unroll
            for (int c = 0; c < 4; c++) acc[i][j][c] = 0.0f;

    for (int kk = 0; kk < DIN; kk += 16) {
        __syncthreads();
        #pragma unroll
        for (int i = 0; i < 2; i++) {
            const int idx = t + i * 256;
            const int row = idx >> 2;
            const int kq  = (idx & 3) * 4;
            float4 v = *(const float4*)(X + (size_t)(mBase + row) * DIN + kk + kq);
            As[kq + 0][row] = f2tf32(v.x);
            As[kq + 1][row] = f2tf32(v.y);
            As[kq + 2][row] = f2tf32(v.z);
            As[kq + 3][row] = f2tf32(v.w);
        }
        #pragma unroll
        for (int i = 0; i < 2; i++) {
            const int idx = t + i * 256;
            const int krow = idx >> 5;
            const int nq   = (idx & 31) * 4;
            float4 v = *(const float4*)(W + (size_t)(kk + krow) * DOUTC + nBase + nq);
            Bs[krow][nq + 0] = f2tf32(v.x);
            Bs[krow][nq + 1] = f2tf32(v.y);
            Bs[krow][nq + 2] = f2tf32(v.z);
            Bs[krow][nq + 3] = f2tf32(v.w);
        }
        __syncthreads();

        #pragma unroll
        for (int ks = 0; ks < 2; ks++) {
            const int kb = ks * 8;
            unsigned a[4][4], b[4][2];
            #pragma unroll
            for (int i = 0; i < 4; i++) {
                a[i][0] = As[kb + tig    ][m0 + i * 16 + g];
                a[i][1] = As[kb + tig    ][m0 + i * 16 + g + 8];
                a[i][2] = As[kb + tig + 4][m0 + i * 16 + g];
                a[i][3] = As[kb + tig + 4][m0 + i * 16 + g + 8];
            }
            #pragma unroll
            for (int j = 0; j < 4; j++) {
                b[j][0] = Bs[kb + tig    ][n0 + j * 8 + g];
                b[j][1] = Bs[kb + tig + 4][n0 + j * 8 + g];
            }
            #pragma unroll
            for (int i = 0; i < 4; i++)
                #pragma unroll
                for (int j = 0; j < 4; j++)
                    mma_tf32(acc[i][j], a[i], b[j]);
        }
    }

    #pragma unroll
    for (int i = 0; i < 4; i++) {
        const size_t r1 = (size_t)(mBase + m0 + i * 16 + g);
        const size_t r2 = r1 + 8;
        #pragma unroll
        for (int j = 0; j < 4; j++) {
            const int col = nBase + n0 + j * 8 + tig * 2;
            *(float2*)(Y + r1 * DOUTC + col) = make_float2(acc[i][j][0], acc[i][j][1]);
            *(float2*)(Y + r2 * DOUTC + col) = make_float2(acc[i][j][2], acc[i][j][3]);
        }
    }
}

// ---------------------------------------------------------------------------
// Kernel 2: fused attention per (b,h). 2-pass flash-style with O = A^T V.
// smem: Kt[48][516] tf32 (K resident, transposed), stats m/r[512],
//       Qt[48][132], Ps[128][132], Vs[128][56]  — total 224768 B dynamic.
// 256 threads = 8 warps; warp owns 16 rows of each 128-row tile.
// ---------------------------------------------------------------------------
#define KT_PITCH 516
#define QT_PITCH 132
#define PS_PITCH 132
#define VS_PITCH 56
#define OFF_MS   99072
#define OFF_RS   101120
#define OFF_QT   103168
#define OFF_PS   128512
#define OFF_VS   196096
#define SMEM_ATT 224768

__global__ __launch_bounds__(256) void attn_fused(const int* __restrict__ Qlen,
                                                  const int* __restrict__ Vlen,
                                                  float* __restrict__ Out) {
    extern __shared__ char smem[];
    unsigned* Kt = (unsigned*)smem;
    float*    mS = (float*)(smem + OFF_MS);
    float*    rS = (float*)(smem + OFF_RS);
    unsigned* Qt = (unsigned*)(smem + OFF_QT);
    unsigned* Ps = (unsigned*)(smem + OFF_PS);
    unsigned* Vs = (unsigned*)(smem + OFF_VS);

    const int blk = blockIdx.x;
    const int b = blk >> 4;
    const int h = blk & 15;
    const int t = threadIdx.x;
    const int lane = t & 31;
    const int w = t >> 5;
    const int g = lane >> 2;
    const int tig = lane & 3;
    const int qr0 = w * 16;

    const int vlen = Vlen[b];
    const int qlen = Qlen[b];

    // ---- load K resident: Kt[d][k] tf32 ----
    for (int i = t; i < 512 * 12; i += 256) {
        const int row = i / 12, dq = (i % 12) * 4;
        float4 v = *(const float4*)&g_k[(size_t)(b * LL + row) * DOUTC + h * DHH + dq];
        Kt[(dq + 0) * KT_PITCH + row] = f2tf32(v.x);
        Kt[(dq + 1) * KT_PITCH + row] = f2tf32(v.y);
        Kt[(dq + 2) * KT_PITCH + row] = f2tf32(v.z);
        Kt[(dq + 3) * KT_PITCH + row] = f2tf32(v.w);
    }

    // ================= PASS 1: softmax stats =================
    for (int qt2 = 0; qt2 < 4; qt2++) {
        __syncthreads();
        for (int i = t; i < 128 * 12; i += 256) {
            const int row = i / 12, dq = (i % 12) * 4;
            float4 v = *(const float4*)&g_q[(size_t)(b * LL + qt2 * 128 + row) * DOUTC + h * DHH + dq];
            Qt[(dq + 0) * QT_PITCH + row] = f2tf32(v.x);
            Qt[(dq + 1) * QT_PITCH + row] = f2tf32(v.y);
            Qt[(dq + 2) * QT_PITCH + row] = f2tf32(v.z);
            Qt[(dq + 3) * QT_PITCH + row] = f2tf32(v.w);
        }
        __syncthreads();

        const int qg0 = qt2 * 128 + qr0 + g;
        const int qg1 = qg0 + 8;
        float m0r = -3.4e38f, m1r = -3.4e38f, l0 = 0.0f, l1 = 0.0f;

        for (int kc = 0; kc < 4; kc++) {
            float acc[16][4];
            #pragma unroll
            for (int nt = 0; nt < 16; nt++)
                #pragma unroll
                for (int c = 0; c < 4; c++) acc[nt][c] = 0.0f;

            #pragma unroll
            for (int kd = 0; kd < 48; kd += 8) {
                unsigned a[4];
                a[0] = Qt[(kd + tig)     * QT_PITCH + qr0 + g];
                a[1] = Qt[(kd + tig)     * QT_PITCH + qr0 + g + 8];
                a[2] = Qt[(kd + tig + 4) * QT_PITCH + qr0 + g];
                a[3] = Qt[(kd + tig + 4) * QT_PITCH + qr0 + g + 8];
                #pragma unroll
                for (int nt = 0; nt < 16; nt++) {
                    unsigned bf[2];
                    const int n = kc * 128 + nt * 8 + g;
                    bf[0] = Kt[(kd + tig)     * KT_PITCH + n];
                    bf[1] = Kt[(kd + tig + 4) * KT_PITCH + n];
                    mma_tf32(acc[nt], a, bf);
                }
            }

            float cm0 = -3.4e38f, cm1 = -3.4e38f;
            #pragma unroll
            for (int nt = 0; nt < 16; nt++)
                #pragma unroll
                for (int c = 0; c < 4; c++) {
                    const int col = kc * 128 + nt * 8 + tig * 2 + (c & 1);
                    float s = acc[nt][c] * SCALEC;
                    if (col >= vlen) s -= NEGC;
                    if (col > ((c < 2) ? qg0 : qg1)) s -= NEGC;
                    acc[nt][c] = s;
                    if (c < 2) cm0 = fmaxf(cm0, s); else cm1 = fmaxf(cm1, s);
                }
            cm0 = fmaxf(cm0, __shfl_xor_sync(0xffffffffu, cm0, 1));
            cm0 = fmaxf(cm0, __shfl_xor_sync(0xffffffffu, cm0, 2));
            cm1 = fmaxf(cm1, __shfl_xor_sync(0xffffffffu, cm1, 1));
            cm1 = fmaxf(cm1, __shfl_xor_sync(0xffffffffu, cm1, 2));
            const float mn0 = fmaxf(m0r, cm0);
            const float mn1 = fmaxf(m1r, cm1);
            float s0 = 0.0f, s1 = 0.0f;
            #pragma unroll
            for (int nt = 0; nt < 16; nt++) {
                s0 += __expf(acc[nt][0] - mn0) + __expf(acc[nt][1] - mn0);
                s1 += __expf(acc[nt][2] - mn1) + __expf(acc[nt][3] - mn1);
            }
            s0 += __shfl_xor_sync(0xffffffffu, s0, 1);
            s0 += __shfl_xor_sync(0xffffffffu, s0, 2);
            s1 += __shfl_xor_sync(0xffffffffu, s1, 1);
            s1 += __shfl_xor_sync(0xffffffffu, s1, 2);
            l0 = l0 * __expf(m0r - mn0) + s0; m0r = mn0;
            l1 = l1 * __expf(m1r - mn1) + s1; m1r = mn1;
        }

        if (tig == 0) {
            mS[qg0] = m0r; rS[qg0] = 1.0f / l0;
            mS[qg1] = m1r; rS[qg1] = 1.0f / l1;
        }
    }

    // ================= PASS 2: O = P^T V per k-tile =================
    for (int kt = 0; kt < 4; kt++) {
        float oacc[6][4];
        #pragma unroll
        for (int nt = 0; nt < 6; nt++)
            #pragma unroll
            for (int c = 0; c < 4; c++) oacc[nt][c] = 0.0f;

        for (int qt2 = 0; qt2 < 4; qt2++) {
            __syncthreads();
            for (int i = t; i < 128 * 12; i += 256) {
                const int row = i / 12, dq = (i % 12) * 4;
                const size_t gofs = (size_t)(b * LL + qt2 * 128 + row) * DOUTC + h * DHH + dq;
                float4 v = *(const float4*)&g_q[gofs];
                Qt[(dq + 0) * QT_PITCH + row] = f2tf32(v.x);
                Qt[(dq + 1) * QT_PITCH + row] = f2tf32(v.y);
                Qt[(dq + 2) * QT_PITCH + row] = f2tf32(v.z);
                Qt[(dq + 3) * QT_PITCH + row] = f2tf32(v.w);
                float4 u = *(const float4*)&g_v[gofs];
                unsigned* vp = &Vs[row * VS_PITCH + dq];
                vp[0] = f2tf32(u.x); vp[1] = f2tf32(u.y);
                vp[2] = f2tf32(u.z); vp[3] = f2tf32(u.w);
            }
            __syncthreads();

            // S tile [128q x 128k]
            float acc[16][4];
            #pragma unroll
            for (int nt = 0; nt < 16; nt++)
                #pragma unroll
                for (int c = 0; c < 4; c++) acc[nt][c] = 0.0f;

            #pragma unroll
            for (int kd = 0; kd < 48; kd += 8) {
                unsigned a[4];
                a[0] = Qt[(kd + tig)     * QT_PITCH + qr0 + g];
                a[1] = Qt[(kd + tig)     * QT_PITCH + qr0 + g + 8];
                a[2] = Qt[(kd + tig + 4) * QT_PITCH + qr0 + g];
                a[3] = Qt[(kd + tig + 4) * QT_PITCH + qr0 + g + 8];
                #pragma unroll
                for (int nt = 0; nt < 16; nt++) {
                    unsigned bf[2];
                    const int n = kt * 128 + nt * 8 + g;
                    bf[0] = Kt[(kd + tig)     * KT_PITCH + n];
                    bf[1] = Kt[(kd + tig + 4) * KT_PITCH + n];
                    mma_tf32(acc[nt], a, bf);
                }
            }

            const int qg0 = qt2 * 128 + qr0 + g;
            const int qg1 = qg0 + 8;
            const float mm0 = mS[qg0], rr0 = rS[qg0];
            const float mm1 = mS[qg1], rr1 = rS[qg1];
            #pragma unroll
            for (int nt = 0; nt < 16; nt++)
                #pragma unroll
                for (int c = 0; c < 4; c++) {
                    const int col = kt * 128 + nt * 8 + tig * 2 + (c & 1);
                    float s = acc[nt][c] * SCALEC;
                    if (col >= vlen) s -= NEGC;
                    if (col > ((c < 2) ? qg0 : qg1)) s -= NEGC;
                    const float p = __expf(s - ((c < 2) ? mm0 : mm1)) * ((c < 2) ? rr0 : rr1);
                    const int rloc = qr0 + g + ((c < 2) ? 0 : 8);
                    Ps[rloc * PS_PITCH + nt * 8 + tig * 2 + (c & 1)] = f2tf32(p);
                }
            __syncthreads();

            // O += P^T V  (m = k_local, n = d, contraction over q_local)
            #pragma unroll 4
            for (int qd = 0; qd < 128; qd += 8) {
                unsigned a[4];
                a[0] = Ps[(qd + tig)     * PS_PITCH + qr0 + g];
                a[1] = Ps[(qd + tig)     * PS_PITCH + qr0 + g + 8];
                a[2] = Ps[(qd + tig + 4) * PS_PITCH + qr0 + g];
                a[3] = Ps[(qd + tig + 4) * PS_PITCH + qr0 + g + 8];
                #pragma unroll
                for (int nt = 0; nt < 6; nt++) {
                    unsigned bf[2];
                    bf[0] = Vs[(qd + tig)     * VS_PITCH + nt * 8 + g];
                    bf[1] = Vs[(qd + tig + 4) * VS_PITCH + nt * 8 + g];
                    mma_tf32(oacc[nt], a, bf);
                }
            }
        }

        // epilogue for this k-tile
        const int kg0 = kt * 128 + qr0 + g;
        const float f0 = (kg0 < qlen) ? 1.0f : 0.0f;
        const float f1 = (kg0 + 8 < qlen) ? 1.0f : 0.0f;
        #pragma unroll
        for (int nt = 0; nt < 6; nt++) {
            const int col = h * DHH + nt * 8 + tig * 2;
            float* o0 = Out + (size_t)(b * LL + kg0) * DOUTC + col;
            *(float2*)o0 = make_float2(oacc[nt][0] * f0, oacc[nt][1] * f0);
            float* o1 = Out + (size_t)(b * LL + kg0 + 8) * DOUTC + col;
            *(float2*)o1 = make_float2(oacc[nt][2] * f1, oacc[nt][3] * f1);
        }
    }
}

// ---------------------------------------------------------------------------
extern "C" void kernel_launch(void* const* d_in, const int* in_sizes, int n_in,
                              void* d_out, int out_size) {
    const float* Qseq = (const float*)d_in[0];
    const float* Kseq = (const float*)d_in[1];
    const float* Vseq = (const float*)d_in[2];
    const float* WQ   = (const float*)d_in[3];
    const float* WK   = (const float*)d_in[4];
    const float* WV   = (const float*)d_in[5];
    const int*   Qlen = (const int*)d_in[6];
    const int*   Vlen = (const int*)d_in[7];

    float *gq, *gk, *gv;
    cudaGetSymbolAddress((void**)&gq, g_q);
    cudaGetSymbolAddress((void**)&gk, g_k);
    cudaGetSymbolAddress((void**)&gv, g_v);

    cudaFuncSetAttribute(attn_fused, cudaFuncAttributeMaxDynamicSharedMemorySize, SMEM_ATT);

    dim3 gproj(6, 128);
    proj_gemm_tc<<<gproj, 256>>>(Qseq, WQ, gq);
    proj_gemm_tc<<<gproj, 256>>>(Kseq, WK, gk);
    proj_gemm_tc<<<gproj, 256>>>(Vseq, WV, gv);

    attn_fused<<<BB * HH, 256, SMEM_ATT>>>(Qlen, Vlen, (float*)d_out);
}

// round 4
// speedup vs baseline: 3.2875x; 1.5379x over previous
#include <cuda_runtime.h>

#define BB 32
#define LL 512
#define DIN 768
#define HH 16
#define DHH 48
#define DOUTC 768
#define M_TOT (BB*LL)
#define NEGC 1e12f
#define SCALEC 0.14433756729740643f   /* 1/sqrt(48) */

// Scratch (static device globals — allowed; no runtime allocation)
__device__ float g_q[(size_t)M_TOT * DOUTC];
__device__ float g_k[(size_t)M_TOT * DOUTC];
__device__ float g_v[(size_t)M_TOT * DOUTC];

__device__ __forceinline__ unsigned f2tf32(float x) {
    unsigned r;
    asm("cvt.rna.tf32.f32 %0, %1;" : "=r"(r) : "f"(x));
    return r;
}

__device__ __forceinline__ void mma_tf32(float* c, const unsigned* a, const unsigned* b) {
    asm volatile(
        "mma.sync.aligned.m16n8k8.row.col.f32.tf32.tf32.f32 "
        "{%0,%1,%2,%3}, {%4,%5,%6,%7}, {%8,%9}, {%0,%1,%2,%3};"
        : "+f"(c[0]), "+f"(c[1]), "+f"(c[2]), "+f"(c[3])
        : "r"(a[0]), "r"(a[1]), "r"(a[2]), "r"(a[3]), "r"(b[0]), "r"(b[1]));
}

// ---------------------------------------------------------------------------
// Kernel 1: TF32 tensor-core projection GEMM (validated R2; pitch 132->136)
// ---------------------------------------------------------------------------
#define PADW 136
__global__ __launch_bounds__(256) void proj_gemm_tc(const float* __restrict__ X,
                                                    const float* __restrict__ W,
                                                    float* __restrict__ Y) {
    __shared__ unsigned As[16][PADW];   // As[k][m]
    __shared__ unsigned Bs[16][PADW];   // Bs[k][n]

    const int t = threadIdx.x;
    const int lane = t & 31;
    const int w = t >> 5;
    const int wm = w >> 2;
    const int wn = w & 3;
    const int g   = lane >> 2;
    const int tig = lane & 3;

    const int mBase = blockIdx.y * 128;
    const int nBase = blockIdx.x * 128;
    const int m0 = wm * 64;
    const int n0 = wn * 32;

    float acc[4][4][4];
    #pragma unroll
    for (int i = 0; i < 4; i++)
        #pragma unroll
        for (int j = 0; j < 4; j++)
            #pragma unroll
            for (int c = 0; c < 4; c++) acc[i][j][c] = 0.0f;

    for (int kk = 0; kk < DIN; kk += 16) {
        __syncthreads();
        #pragma unroll
        for (int i = 0; i < 2; i++) {
            const int idx = t + i * 256;
            const int row = idx >> 2;
            const int kq  = (idx & 3) * 4;
            float4 v = *(const float4*)(X + (size_t)(mBase + row) * DIN + kk + kq);
            As[kq + 0][row] = f2tf32(v.x);
            As[kq + 1][row] = f2tf32(v.y);
            As[kq + 2][row] = f2tf32(v.z);
            As[kq + 3][row] = f2tf32(v.w);
        }
        #pragma unroll
        for (int i = 0; i < 2; i++) {
            const int idx = t + i * 256;
            const int krow = idx >> 5;
            const int nq   = (idx & 31) * 4;
            float4 v = *(const float4*)(W + (size_t)(kk + krow) * DOUTC + nBase + nq);
            Bs[krow][nq + 0] = f2tf32(v.x);
            Bs[krow][nq + 1] = f2tf32(v.y);
            Bs[krow][nq + 2] = f2tf32(v.z);
            Bs[krow][nq + 3] = f2tf32(v.w);
        }
        __syncthreads();

        #pragma unroll
        for (int ks = 0; ks < 2; ks++) {
            const int kb = ks * 8;
            unsigned a[4][4], b[4][2];
            #pragma unroll
            for (int i = 0; i < 4; i++) {
                a[i][0] = As[kb + tig    ][m0 + i * 16 + g];
                a[i][1] = As[kb + tig    ][m0 + i * 16 + g + 8];
                a[i][2] = As[kb + tig + 4][m0 + i * 16 + g];
                a[i][3] = As[kb + tig + 4][m0 + i * 16 + g + 8];
            }
            #pragma unroll
            for (int j = 0; j < 4; j++) {
                b[j][0] = Bs[kb + tig    ][n0 + j * 8 + g];
                b[j][1] = Bs[kb + tig + 4][n0 + j * 8 + g];
            }
            #pragma unroll
            for (int i = 0; i < 4; i++)
                #pragma unroll
                for (int j = 0; j < 4; j++)
                    mma_tf32(acc[i][j], a[i], b[j]);
        }
    }

    #pragma unroll
    for (int i = 0; i < 4; i++) {
        const size_t r1 = (size_t)(mBase + m0 + i * 16 + g);
        const size_t r2 = r1 + 8;
        #pragma unroll
        for (int j = 0; j < 4; j++) {
            const int col = nBase + n0 + j * 8 + tig * 2;
            *(float2*)(Y + r1 * DOUTC + col) = make_float2(acc[i][j][0], acc[i][j][1]);
            *(float2*)(Y + r2 * DOUTC + col) = make_float2(acc[i][j][2], acc[i][j][3]);
        }
    }
}

// ---------------------------------------------------------------------------
// Kernel 2: fused attention per (b,h), 512 threads / 16 warps.
// S^T = K·Q^T formulation; fixed-reference softmax (no max pass); 1/l folded
// into V; causal tile skipping; per-warp P bounce buffer (syncwarp only).
// ---------------------------------------------------------------------------
#define KR_PITCH 52
#define QT_PITCH 136
#define VS_PITCH 56
#define PB_PITCH 12
#define OFF_QT   106496
#define OFF_VS   132608
#define OFF_PB   161280
#define OFF_SSUM 173568
#define OFF_LS   181760
#define SMEM_ATT 183808

__global__ __launch_bounds__(512, 1) void attn_fused(const int* __restrict__ Qlen,
                                                     const int* __restrict__ Vlen,
                                                     float* __restrict__ Out) {
    extern __shared__ char smem[];
    unsigned* Kr    = (unsigned*)smem;                  // [512][52] K row-major
    unsigned* Qt    = (unsigned*)(smem + OFF_QT);       // [48][136] Q^T tile
    unsigned* Vs    = (unsigned*)(smem + OFF_VS);       // [128][56] V tile (pre-scaled)
    unsigned* Pball = (unsigned*)(smem + OFF_PB);       // per-warp [16][12]
    float*    sSum  = (float*)(smem + OFF_SSUM);        // [16][128]
    float*    lS    = (float*)(smem + OFF_LS);          // [512] inverse sums

    const int b = blockIdx.x >> 4, h = blockIdx.x & 15;
    const int t = threadIdx.x, lane = t & 31, w = t >> 5;
    const int g = lane >> 2, tig = lane & 3, w8 = w & 7;
    const int vlen = Vlen[b], qlen = Qlen[b];
    const float bias = (vlen == 0) ? NEGC : 0.0f;

    // ---- K resident, row-major [k][d] tf32 ----
    for (int i = t; i < 512 * 12; i += 512) {
        const int row = i / 12, dq = (i % 12) * 4;
        float4 v = *(const float4*)&g_k[(size_t)(b * LL + row) * DOUTC + h * DHH + dq];
        *(uint4*)&Kr[row * KR_PITCH + dq] =
            make_uint4(f2tf32(v.x), f2tf32(v.y), f2tf32(v.z), f2tf32(v.w));
    }

    // ================= PHASE A: column sums of exp(S) =================
    for (int qt = 0; qt < 4; qt++) {
        __syncthreads();
        for (int i = t; i < 128 * 12; i += 512) {
            const int row = i / 12, dq = (i % 12) * 4;
            float4 v = *(const float4*)&g_q[(size_t)(b * LL + qt * 128 + row) * DOUTC + h * DHH + dq];
            Qt[(dq + 0) * QT_PITCH + row] = f2tf32(v.x);
            Qt[(dq + 1) * QT_PITCH + row] = f2tf32(v.y);
            Qt[(dq + 2) * QT_PITCH + row] = f2tf32(v.z);
            Qt[(dq + 3) * QT_PITCH + row] = f2tf32(v.w);
        }
        __syncthreads();

        float csum[16][2];
        #pragma unroll
        for (int nt = 0; nt < 16; nt++) { csum[nt][0] = 0.0f; csum[nt][1] = 0.0f; }
        const int kmaxc = qt * 128 + 128;   // causal: rows >= this are fully masked

        for (int half = 0; half < 2; half++) {
            const int mr = half * 256 + w * 16;
            if (mr >= kmaxc) continue;
            const int kg0 = mr + g, kg1 = mr + g + 8;
            #pragma unroll
            for (int nb = 0; nb < 2; nb++) {
                float acc[8][4];
                #pragma unroll
                for (int nl = 0; nl < 8; nl++)
                    #pragma unroll
                    for (int c = 0; c < 4; c++) acc[nl][c] = 0.0f;
                #pragma unroll
                for (int kd = 0; kd < 48; kd += 8) {
                    unsigned a[4];
                    a[0] = Kr[(mr + g)     * KR_PITCH + kd + tig];
                    a[1] = Kr[(mr + g + 8) * KR_PITCH + kd + tig];
                    a[2] = Kr[(mr + g)     * KR_PITCH + kd + tig + 4];
                    a[3] = Kr[(mr + g + 8) * KR_PITCH + kd + tig + 4];
                    #pragma unroll
                    for (int nl = 0; nl < 8; nl++) {
                        const int n = (nb * 8 + nl) * 8 + g;
                        unsigned bf[2] = { Qt[(kd + tig) * QT_PITCH + n],
                                           Qt[(kd + tig + 4) * QT_PITCH + n] };
                        mma_tf32(acc[nl], a, bf);
                    }
                }
                #pragma unroll
                for (int nl = 0; nl < 8; nl++) {
                    const int nt = nb * 8 + nl;
                    const int q0 = qt * 128 + nt * 8 + tig * 2;
                    float s0 = acc[nl][0] * SCALEC, s1 = acc[nl][1] * SCALEC;
                    float s2 = acc[nl][2] * SCALEC, s3 = acc[nl][3] * SCALEC;
                    if (kg0 >= vlen) { s0 -= NEGC; s1 -= NEGC; }
                    if (kg1 >= vlen) { s2 -= NEGC; s3 -= NEGC; }
                    if (kg0 > q0)     s0 -= NEGC;
                    if (kg0 > q0 + 1) s1 -= NEGC;
                    if (kg1 > q0)     s2 -= NEGC;
                    if (kg1 > q0 + 1) s3 -= NEGC;
                    csum[nt][0] += __expf(s0 + bias) + __expf(s2 + bias);
                    csum[nt][1] += __expf(s1 + bias) + __expf(s3 + bias);
                }
            }
        }
        // reduce over g lanes (rows), then write per-warp partials
        #pragma unroll
        for (int nt = 0; nt < 16; nt++)
            #pragma unroll
            for (int p = 0; p < 2; p++) {
                float v = csum[nt][p];
                v += __shfl_xor_sync(0xffffffffu, v, 4);
                v += __shfl_xor_sync(0xffffffffu, v, 8);
                v += __shfl_xor_sync(0xffffffffu, v, 16);
                csum[nt][p] = v;
            }
        if (g == 0) {
            #pragma unroll
            for (int nt = 0; nt < 16; nt++)
                *(float2*)&sSum[w * 128 + nt * 8 + tig * 2] =
                    make_float2(csum[nt][0], csum[nt][1]);
        }
        __syncthreads();
        if (t < 128) {
            float l = 0.0f;
            #pragma unroll
            for (int w2 = 0; w2 < 16; w2++) l += sSum[w2 * 128 + t];
            lS[qt * 128 + t] = 1.0f / l;
        }
    }

    // ================= PHASE B: O = exp(S)^T · (V/l) =================
    for (int ktp = 0; ktp < 4; ktp += 2) {
        const int kt = ktp + (w >> 3);
        const int krow0 = kt * 128 + w8 * 16;
        float oacc[6][4];
        #pragma unroll
        for (int nd = 0; nd < 6; nd++)
            #pragma unroll
            for (int c = 0; c < 4; c++) oacc[nd][c] = 0.0f;

        for (int qt = ktp; qt < 4; qt++) {
            __syncthreads();
            for (int i = t; i < 128 * 12; i += 512) {
                const int row = i / 12, dq = (i % 12) * 4;
                const size_t gof = (size_t)(b * LL + qt * 128 + row) * DOUTC + h * DHH + dq;
                float4 v = *(const float4*)&g_q[gof];
                Qt[(dq + 0) * QT_PITCH + row] = f2tf32(v.x);
                Qt[(dq + 1) * QT_PITCH + row] = f2tf32(v.y);
                Qt[(dq + 2) * QT_PITCH + row] = f2tf32(v.z);
                Qt[(dq + 3) * QT_PITCH + row] = f2tf32(v.w);
                float4 u = *(const float4*)&g_v[gof];
                const float r = lS[qt * 128 + row];
                *(uint4*)&Vs[row * VS_PITCH + dq] =
                    make_uint4(f2tf32(u.x * r), f2tf32(u.y * r),
                               f2tf32(u.z * r), f2tf32(u.w * r));
            }
            __syncthreads();
            if (qt < kt) continue;   // fully causal-masked (exact: exp underflows to 0)

            float acc[16][4];
            #pragma unroll
            for (int nt = 0; nt < 16; nt++)
                #pragma unroll
                for (int c = 0; c < 4; c++) acc[nt][c] = 0.0f;
            #pragma unroll
            for (int kd = 0; kd < 48; kd += 8) {
                unsigned a[4];
                a[0] = Kr[(krow0 + g)     * KR_PITCH + kd + tig];
                a[1] = Kr[(krow0 + g + 8) * KR_PITCH + kd + tig];
                a[2] = Kr[(krow0 + g)     * KR_PITCH + kd + tig + 4];
                a[3] = Kr[(krow0 + g + 8) * KR_PITCH + kd + tig + 4];
                #pragma unroll
                for (int nt = 0; nt < 16; nt++) {
                    const int n = nt * 8 + g;
                    unsigned bf[2] = { Qt[(kd + tig) * QT_PITCH + n],
                                       Qt[(kd + tig + 4) * QT_PITCH + n] };
                    mma_tf32(acc[nt], a, bf);
                }
            }

            const int kg0 = krow0 + g, kg1 = kg0 + 8;
            unsigned* Pb = Pball + w * (16 * PB_PITCH);
            #pragma unroll
            for (int nt = 0; nt < 16; nt++) {
                const int q0 = qt * 128 + nt * 8 + tig * 2;
                float s0 = acc[nt][0] * SCALEC, s1 = acc[nt][1] * SCALEC;
                float s2 = acc[nt][2] * SCALEC, s3 = acc[nt][3] * SCALEC;
                if (kg0 >= vlen) { s0 -= NEGC; s1 -= NEGC; }
                if (kg1 >= vlen) { s2 -= NEGC; s3 -= NEGC; }
                if (kg0 > q0)     s0 -= NEGC;
                if (kg0 > q0 + 1) s1 -= NEGC;
                if (kg1 > q0)     s2 -= NEGC;
                if (kg1 > q0 + 1) s3 -= NEGC;
                const float e0 = __expf(s0 + bias), e1 = __expf(s1 + bias);
                const float e2 = __expf(s2 + bias), e3 = __expf(s3 + bias);
                __syncwarp();
                *(uint2*)&Pb[g * PB_PITCH + tig * 2]       = make_uint2(f2tf32(e0), f2tf32(e1));
                *(uint2*)&Pb[(g + 8) * PB_PITCH + tig * 2] = make_uint2(f2tf32(e2), f2tf32(e3));
                __syncwarp();
                unsigned ap[4];
                ap[0] = Pb[g * PB_PITCH + tig];
                ap[1] = Pb[(g + 8) * PB_PITCH + tig];
                ap[2] = Pb[g * PB_PITCH + tig + 4];
                ap[3] = Pb[(g + 8) * PB_PITCH + tig + 4];
                #pragma unroll
                for (int nd = 0; nd < 6; nd++) {
                    unsigned bf[2] = { Vs[(nt * 8 + tig) * VS_PITCH + nd * 8 + g],
                                       Vs[(nt * 8 + tig + 4) * VS_PITCH + nd * 8 + g] };
                    mma_tf32(oacc[nd], ap, bf);
                }
            }
        }

        const int kg0 = krow0 + g;
        const float f0 = (kg0 < qlen) ? 1.0f : 0.0f;
        const float f1 = (kg0 + 8 < qlen) ? 1.0f : 0.0f;
        #pragma unroll
        for (int nd = 0; nd < 6; nd++) {
            const int col = h * DHH + nd * 8 + tig * 2;
            *(float2*)(Out + (size_t)(b * LL + kg0) * DOUTC + col) =
                make_float2(oacc[nd][0] * f0, oacc[nd][1] * f0);
            *(float2*)(Out + (size_t)(b * LL + kg0 + 8) * DOUTC + col) =
                make_float2(oacc[nd][2] * f1, oacc[nd][3] * f1);
        }
    }
}

// ---------------------------------------------------------------------------
extern "C" void kernel_launch(void* const* d_in, const int* in_sizes, int n_in,
                              void* d_out, int out_size) {
    const float* Qseq = (const float*)d_in[0];
    const float* Kseq = (const float*)d_in[1];
    const float* Vseq = (const float*)d_in[2];
    const float* WQ   = (const float*)d_in[3];
    const float* WK   = (const float*)d_in[4];
    const float* WV   = (const float*)d_in[5];
    const int*   Qlen = (const int*)d_in[6];
    const int*   Vlen = (const int*)d_in[7];

    float *gq, *gk, *gv;
    cudaGetSymbolAddress((void**)&gq, g_q);
    cudaGetSymbolAddress((void**)&gk, g_k);
    cudaGetSymbolAddress((void**)&gv, g_v);

    cudaFuncSetAttribute(attn_fused, cudaFuncAttributeMaxDynamicSharedMemorySize, SMEM_ATT);

    dim3 gproj(6, 128);
    proj_gemm_tc<<<gproj, 256>>>(Qseq, WQ, gq);
    proj_gemm_tc<<<gproj, 256>>>(Kseq, WK, gk);
    proj_gemm_tc<<<gproj, 256>>>(Vseq, WV, gv);

    attn_fused<<<BB * HH, 512, SMEM_ATT>>>(Qlen, Vlen, (float*)d_out);
}

// round 5
// speedup vs baseline: 3.4709x; 1.0558x over previous
#include <cuda_runtime.h>

#define BB 32
#define LL 512
#define DIN 768
#define HH 16
#define DHH 48
#define DOUTC 768
#define M_TOT (BB*LL)
#define NEGC 1e12f
#define SCALEC 0.14433756729740643f   /* 1/sqrt(48) */

// Scratch (static device globals — allowed; no runtime allocation)
__device__ float g_q[(size_t)M_TOT * DOUTC];
__device__ float g_k[(size_t)M_TOT * DOUTC];
__device__ float g_v[(size_t)M_TOT * DOUTC];

__device__ __forceinline__ unsigned f2tf32(float x) {
    unsigned r;
    asm("cvt.rna.tf32.f32 %0, %1;" : "=r"(r) : "f"(x));
    return r;
}

__device__ __forceinline__ void mma_tf32(float* c, const unsigned* a, const unsigned* b) {
    asm volatile(
        "mma.sync.aligned.m16n8k8.row.col.f32.tf32.tf32.f32 "
        "{%0,%1,%2,%3}, {%4,%5,%6,%7}, {%8,%9}, {%0,%1,%2,%3};"
        : "+f"(c[0]), "+f"(c[1]), "+f"(c[2]), "+f"(c[3])
        : "r"(a[0]), "r"(a[1]), "r"(a[2]), "r"(a[3]), "r"(b[0]), "r"(b[1]));
}

// ---------------------------------------------------------------------------
// Kernel 1: TF32 tensor-core projection GEMM  Y[16384,768] = X @ W[768,768]
// R5: ping-pong double-buffered smem, 1 sync per K-chunk, prefetch LDG.
// ---------------------------------------------------------------------------
#define PADW 136
#define NCHUNK (DIN / 16)
__global__ __launch_bounds__(256, 2) void proj_gemm_tc(const float* __restrict__ X,
                                                       const float* __restrict__ W,
                                                       float* __restrict__ Y) {
    __shared__ unsigned As[2][16][PADW];   // As[buf][k][m]
    __shared__ unsigned Bs[2][16][PADW];   // Bs[buf][k][n]

    const int t = threadIdx.x;
    const int lane = t & 31;
    const int w = t >> 5;
    const int wm = w >> 2;
    const int wn = w & 3;
    const int g   = lane >> 2;
    const int tig = lane & 3;

    const int mBase = blockIdx.y * 128;
    const int nBase = blockIdx.x * 128;
    const int m0 = wm * 64;
    const int n0 = wn * 32;

    // per-thread global-load coordinates (2 float4 for A, 2 for B per chunk)
    int aRow[2], aKq[2], bKrow[2], bNq[2];
    #pragma unroll
    for (int i = 0; i < 2; i++) {
        const int idx = t + i * 256;
        aRow[i]  = idx >> 2;            // 0..127
        aKq[i]   = (idx & 3) * 4;       // 0,4,8,12
        bKrow[i] = idx >> 5;            // 0..15
        bNq[i]   = (idx & 31) * 4;      // 0..124
    }

    float acc[4][4][4];
    #pragma unroll
    for (int i = 0; i < 4; i++)
        #pragma unroll
        for (int j = 0; j < 4; j++)
            #pragma unroll
            for (int c = 0; c < 4; c++) acc[i][j][c] = 0.0f;

    float4 av[2], bv[2];
    // prefetch chunk 0
    #pragma unroll
    for (int i = 0; i < 2; i++) {
        av[i] = *(const float4*)(X + (size_t)(mBase + aRow[i]) * DIN + aKq[i]);
        bv[i] = *(const float4*)(W + (size_t)bKrow[i] * DOUTC + nBase + bNq[i]);
    }
    // stage chunk 0 -> buf 0
    #pragma unroll
    for (int i = 0; i < 2; i++) {
        As[0][aKq[i] + 0][aRow[i]] = f2tf32(av[i].x);
        As[0][aKq[i] + 1][aRow[i]] = f2tf32(av[i].y);
        As[0][aKq[i] + 2][aRow[i]] = f2tf32(av[i].z);
        As[0][aKq[i] + 3][aRow[i]] = f2tf32(av[i].w);
        Bs[0][bKrow[i]][bNq[i] + 0] = f2tf32(bv[i].x);
        Bs[0][bKrow[i]][bNq[i] + 1] = f2tf32(bv[i].y);
        Bs[0][bKrow[i]][bNq[i] + 2] = f2tf32(bv[i].z);
        Bs[0][bKrow[i]][bNq[i] + 3] = f2tf32(bv[i].w);
    }
    __syncthreads();

    for (int c = 0; c < NCHUNK; c++) {
        const int cur = c & 1;
        const bool more = (c + 1 < NCHUNK);
        if (more) {
            const int kk = (c + 1) * 16;
            #pragma unroll
            for (int i = 0; i < 2; i++) {
                av[i] = *(const float4*)(X + (size_t)(mBase + aRow[i]) * DIN + kk + aKq[i]);
                bv[i] = *(const float4*)(W + (size_t)(kk + bKrow[i]) * DOUTC + nBase + bNq[i]);
            }
        }

        #pragma unroll
        for (int ks = 0; ks < 2; ks++) {
            const int kb = ks * 8;
            unsigned a[4][4], b[4][2];
            #pragma unroll
            for (int i = 0; i < 4; i++) {
                a[i][0] = As[cur][kb + tig    ][m0 + i * 16 + g];
                a[i][1] = As[cur][kb + tig    ][m0 + i * 16 + g + 8];
                a[i][2] = As[cur][kb + tig + 4][m0 + i * 16 + g];
                a[i][3] = As[cur][kb + tig + 4][m0 + i * 16 + g + 8];
            }
            #pragma unroll
            for (int j = 0; j < 4; j++) {
                b[j][0] = Bs[cur][kb + tig    ][n0 + j * 8 + g];
                b[j][1] = Bs[cur][kb + tig + 4][n0 + j * 8 + g];
            }
            #pragma unroll
            for (int i = 0; i < 4; i++)
                #pragma unroll
                for (int j = 0; j < 4; j++)
                    mma_tf32(acc[i][j], a[i], b[j]);
        }

        if (more) {
            const int nxt = cur ^ 1;
            #pragma unroll
            for (int i = 0; i < 2; i++) {
                As[nxt][aKq[i] + 0][aRow[i]] = f2tf32(av[i].x);
                As[nxt][aKq[i] + 1][aRow[i]] = f2tf32(av[i].y);
                As[nxt][aKq[i] + 2][aRow[i]] = f2tf32(av[i].z);
                As[nxt][aKq[i] + 3][aRow[i]] = f2tf32(av[i].w);
                Bs[nxt][bKrow[i]][bNq[i] + 0] = f2tf32(bv[i].x);
                Bs[nxt][bKrow[i]][bNq[i] + 1] = f2tf32(bv[i].y);
                Bs[nxt][bKrow[i]][bNq[i] + 2] = f2tf32(bv[i].z);
                Bs[nxt][bKrow[i]][bNq[i] + 3] = f2tf32(bv[i].w);
            }
        }
        __syncthreads();
    }

    #pragma unroll
    for (int i = 0; i < 4; i++) {
        const size_t r1 = (size_t)(mBase + m0 + i * 16 + g);
        const size_t r2 = r1 + 8;
        #pragma unroll
        for (int j = 0; j < 4; j++) {
            const int col = nBase + n0 + j * 8 + tig * 2;
            *(float2*)(Y + r1 * DOUTC + col) = make_float2(acc[i][j][0], acc[i][j][1]);
            *(float2*)(Y + r2 * DOUTC + col) = make_float2(acc[i][j][2], acc[i][j][3]);
        }
    }
}

// ---------------------------------------------------------------------------
// Kernel 2: fused attention per (b,h), 512 threads / 16 warps. (unchanged R4)
// ---------------------------------------------------------------------------
#define KR_PITCH 52
#define QT_PITCH 136
#define VS_PITCH 56
#define PB_PITCH 12
#define OFF_QT   106496
#define OFF_VS   132608
#define OFF_PB   161280
#define OFF_SSUM 173568
#define OFF_LS   181760
#define SMEM_ATT 183808

__global__ __launch_bounds__(512, 1) void attn_fused(const int* __restrict__ Qlen,
                                                     const int* __restrict__ Vlen,
                                                     float* __restrict__ Out) {
    extern __shared__ char smem[];
    unsigned* Kr    = (unsigned*)smem;                  // [512][52] K row-major
    unsigned* Qt    = (unsigned*)(smem + OFF_QT);       // [48][136] Q^T tile
    unsigned* Vs    = (unsigned*)(smem + OFF_VS);       // [128][56] V tile (pre-scaled)
    unsigned* Pball = (unsigned*)(smem + OFF_PB);       // per-warp [16][12]
    float*    sSum  = (float*)(smem + OFF_SSUM);        // [16][128]
    float*    lS    = (float*)(smem + OFF_LS);          // [512] inverse sums

    const int b = blockIdx.x >> 4, h = blockIdx.x & 15;
    const int t = threadIdx.x, lane = t & 31, w = t >> 5;
    const int g = lane >> 2, tig = lane & 3, w8 = w & 7;
    const int vlen = Vlen[b], qlen = Qlen[b];
    const float bias = (vlen == 0) ? NEGC : 0.0f;

    // ---- K resident, row-major [k][d] tf32 ----
    for (int i = t; i < 512 * 12; i += 512) {
        const int row = i / 12, dq = (i % 12) * 4;
        float4 v = *(const float4*)&g_k[(size_t)(b * LL + row) * DOUTC + h * DHH + dq];
        *(uint4*)&Kr[row * KR_PITCH + dq] =
            make_uint4(f2tf32(v.x), f2tf32(v.y), f2tf32(v.z), f2tf32(v.w));
    }

    // ================= PHASE A: column sums of exp(S) =================
    for (int qt = 0; qt < 4; qt++) {
        __syncthreads();
        for (int i = t; i < 128 * 12; i += 512) {
            const int row = i / 12, dq = (i % 12) * 4;
            float4 v = *(const float4*)&g_q[(size_t)(b * LL + qt * 128 + row) * DOUTC + h * DHH + dq];
            Qt[(dq + 0) * QT_PITCH + row] = f2tf32(v.x);
            Qt[(dq + 1) * QT_PITCH + row] = f2tf32(v.y);
            Qt[(dq + 2) * QT_PITCH + row] = f2tf32(v.z);
            Qt[(dq + 3) * QT_PITCH + row] = f2tf32(v.w);
        }
        __syncthreads();

        float csum[16][2];
        #pragma unroll
        for (int nt = 0; nt < 16; nt++) { csum[nt][0] = 0.0f; csum[nt][1] = 0.0f; }
        const int kmaxc = qt * 128 + 128;   // causal: rows >= this are fully masked

        for (int half = 0; half < 2; half++) {
            const int mr = half * 256 + w * 16;
            if (mr >= kmaxc) continue;
            const int kg0 = mr + g, kg1 = mr + g + 8;
            #pragma unroll
            for (int nb = 0; nb < 2; nb++) {
                float acc[8][4];
                #pragma unroll
                for (int nl = 0; nl < 8; nl++)
                    #pragma unroll
                    for (int c = 0; c < 4; c++) acc[nl][c] = 0.0f;
                #pragma unroll
                for (int kd = 0; kd < 48; kd += 8) {
                    unsigned a[4];
                    a[0] = Kr[(mr + g)     * KR_PITCH + kd + tig];
                    a[1] = Kr[(mr + g + 8) * KR_PITCH + kd + tig];
                    a[2] = Kr[(mr + g)     * KR_PITCH + kd + tig + 4];
                    a[3] = Kr[(mr + g + 8) * KR_PITCH + kd + tig + 4];
                    #pragma unroll
                    for (int nl = 0; nl < 8; nl++) {
                        const int n = (nb * 8 + nl) * 8 + g;
                        unsigned bf[2] = { Qt[(kd + tig) * QT_PITCH + n],
                                           Qt[(kd + tig + 4) * QT_PITCH + n] };
                        mma_tf32(acc[nl], a, bf);
                    }
                }
                #pragma unroll
                for (int nl = 0; nl < 8; nl++) {
                    const int nt = nb * 8 + nl;
                    const int q0 = qt * 128 + nt * 8 + tig * 2;
                    float s0 = acc[nl][0] * SCALEC, s1 = acc[nl][1] * SCALEC;
                    float s2 = acc[nl][2] * SCALEC, s3 = acc[nl][3] * SCALEC;
                    if (kg0 >= vlen) { s0 -= NEGC; s1 -= NEGC; }
                    if (kg1 >= vlen) { s2 -= NEGC; s3 -= NEGC; }
                    if (kg0 > q0)     s0 -= NEGC;
                    if (kg0 > q0 + 1) s1 -= NEGC;
                    if (kg1 > q0)     s2 -= NEGC;
                    if (kg1 > q0 + 1) s3 -= NEGC;
                    csum[nt][0] += __expf(s0 + bias) + __expf(s2 + bias);
                    csum[nt][1] += __expf(s1 + bias) + __expf(s3 + bias);
                }
            }
        }
        // reduce over g lanes (rows), then write per-warp partials
        #pragma unroll
        for (int nt = 0; nt < 16; nt++)
            #pragma unroll
            for (int p = 0; p < 2; p++) {
                float v = csum[nt][p];
                v += __shfl_xor_sync(0xffffffffu, v, 4);
                v += __shfl_xor_sync(0xffffffffu, v, 8);
                v += __shfl_xor_sync(0xffffffffu, v, 16);
                csum[nt][p] = v;
            }
        if (g == 0) {
            #pragma unroll
            for (int nt = 0; nt < 16; nt++)
                *(float2*)&sSum[w * 128 + nt * 8 + tig * 2] =
                    make_float2(csum[nt][0], csum[nt][1]);
        }
        __syncthreads();
        if (t < 128) {
            float l = 0.0f;
            #pragma unroll
            for (int w2 = 0; w2 < 16; w2++) l += sSum[w2 * 128 + t];
            lS[qt * 128 + t] = 1.0f / l;
        }
    }

    // ================= PHASE B: O = exp(S)^T · (V/l) =================
    for (int ktp = 0; ktp < 4; ktp += 2) {
        const int kt = ktp + (w >> 3);
        const int krow0 = kt * 128 + w8 * 16;
        float oacc[6][4];
        #pragma unroll
        for (int nd = 0; nd < 6; nd++)
            #pragma unroll
            for (int c = 0; c < 4; c++) oacc[nd][c] = 0.0f;

        for (int qt = ktp; qt < 4; qt++) {
            __syncthreads();
            for (int i = t; i < 128 * 12; i += 512) {
                const int row = i / 12, dq = (i % 12) * 4;
                const size_t gof = (size_t)(b * LL + qt * 128 + row) * DOUTC + h * DHH + dq;
                float4 v = *(const float4*)&g_q[gof];
                Qt[(dq + 0) * QT_PITCH + row] = f2tf32(v.x);
                Qt[(dq + 1) * QT_PITCH + row] = f2tf32(v.y);
                Qt[(dq + 2) * QT_PITCH + row] = f2tf32(v.z);
                Qt[(dq + 3) * QT_PITCH + row] = f2tf32(v.w);
                float4 u = *(const float4*)&g_v[gof];
                const float r = lS[qt * 128 + row];
                *(uint4*)&Vs[row * VS_PITCH + dq] =
                    make_uint4(f2tf32(u.x * r), f2tf32(u.y * r),
                               f2tf32(u.z * r), f2tf32(u.w * r));
            }
            __syncthreads();
            if (qt < kt) continue;   // fully causal-masked (exact: exp underflows to 0)

            float acc[16][4];
            #pragma unroll
            for (int nt = 0; nt < 16; nt++)
                #pragma unroll
                for (int c = 0; c < 4; c++) acc[nt][c] = 0.0f;
            #pragma unroll
            for (int kd = 0; kd < 48; kd += 8) {
                unsigned a[4];
                a[0] = Kr[(krow0 + g)     * KR_PITCH + kd + tig];
                a[1] = Kr[(krow0 + g + 8) * KR_PITCH + kd + tig];
                a[2] = Kr[(krow0 + g)     * KR_PITCH + kd + tig + 4];
                a[3] = Kr[(krow0 + g + 8) * KR_PITCH + kd + tig + 4];
                #pragma unroll
                for (int nt = 0; nt < 16; nt++) {
                    const int n = nt * 8 + g;
                    unsigned bf[2] = { Qt[(kd + tig) * QT_PITCH + n],
                                       Qt[(kd + tig + 4) * QT_PITCH + n] };
                    mma_tf32(acc[nt], a, bf);
                }
            }

            const int kg0 = krow0 + g, kg1 = kg0 + 8;
            unsigned* Pb = Pball + w * (16 * PB_PITCH);
            #pragma unroll
            for (int nt = 0; nt < 16; nt++) {
                const int q0 = qt * 128 + nt * 8 + tig * 2;
                float s0 = acc[nt][0] * SCALEC, s1 = acc[nt][1] * SCALEC;
                float s2 = acc[nt][2] * SCALEC, s3 = acc[nt][3] * SCALEC;
                if (kg0 >= vlen) { s0 -= NEGC; s1 -= NEGC; }
                if (kg1 >= vlen) { s2 -= NEGC; s3 -= NEGC; }
                if (kg0 > q0)     s0 -= NEGC;
                if (kg0 > q0 + 1) s1 -= NEGC;
                if (kg1 > q0)     s2 -= NEGC;
                if (kg1 > q0 + 1) s3 -= NEGC;
                const float e0 = __expf(s0 + bias), e1 = __expf(s1 + bias);
                const float e2 = __expf(s2 + bias), e3 = __expf(s3 + bias);
                __syncwarp();
                *(uint2*)&Pb[g * PB_PITCH + tig * 2]       = make_uint2(f2tf32(e0), f2tf32(e1));
                *(uint2*)&Pb[(g + 8) * PB_PITCH + tig * 2] = make_uint2(f2tf32(e2), f2tf32(e3));
                __syncwarp();
                unsigned ap[4];
                ap[0] = Pb[g * PB_PITCH + tig];
                ap[1] = Pb[(g + 8) * PB_PITCH + tig];
                ap[2] = Pb[g * PB_PITCH + tig + 4];
                ap[3] = Pb[(g + 8) * PB_PITCH + tig + 4];
                #pragma unroll
                for (int nd = 0; nd < 6; nd++) {
                    unsigned bf[2] = { Vs[(nt * 8 + tig) * VS_PITCH + nd * 8 + g],
                                       Vs[(nt * 8 + tig + 4) * VS_PITCH + nd * 8 + g] };
                    mma_tf32(oacc[nd], ap, bf);
                }
            }
        }

        const int kg0 = krow0 + g;
        const float f0 = (kg0 < qlen) ? 1.0f : 0.0f;
        const float f1 = (kg0 + 8 < qlen) ? 1.0f : 0.0f;
        #pragma unroll
        for (int nd = 0; nd < 6; nd++) {
            const int col = h * DHH + nd * 8 + tig * 2;
            *(float2*)(Out + (size_t)(b * LL + kg0) * DOUTC + col) =
                make_float2(oacc[nd][0] * f0, oacc[nd][1] * f0);
            *(float2*)(Out + (size_t)(b * LL + kg0 + 8) * DOUTC + col) =
                make_float2(oacc[nd][2] * f1, oacc[nd][3] * f1);
        }
    }
}

// ---------------------------------------------------------------------------
extern "C" void kernel_launch(void* const* d_in, const int* in_sizes, int n_in,
                              void* d_out, int out_size) {
    const float* Qseq = (const float*)d_in[0];
    const float* Kseq = (const float*)d_in[1];
    const float* Vseq = (const float*)d_in[2];
    const float* WQ   = (const float*)d_in[3];
    const float* WK   = (const float*)d_in[4];
    const float* WV   = (const float*)d_in[5];
    const int*   Qlen = (const int*)d_in[6];
    const int*   Vlen = (const int*)d_in[7];

    float *gq, *gk, *gv;
    cudaGetSymbolAddress((void**)&gq, g_q);
    cudaGetSymbolAddress((void**)&gk, g_k);
    cudaGetSymbolAddress((void**)&gv, g_v);

    cudaFuncSetAttribute(attn_fused, cudaFuncAttributeMaxDynamicSharedMemorySize, SMEM_ATT);

    dim3 gproj(6, 128);
    proj_gemm_tc<<<gproj, 256>>>(Qseq, WQ, gq);
    proj_gemm_tc<<<gproj, 256>>>(Kseq, WK, gk);
    proj_gemm_tc<<<gproj, 256>>>(Vseq, WV, gv);

    attn_fused<<<BB * HH, 512, SMEM_ATT>>>(Qlen, Vlen, (float*)d_out);
}

// round 7
// speedup vs baseline: 4.6253x; 1.3326x over previous
#include <cuda_runtime.h>
#include <cuda_fp16.h>
#include <cstdint>

#define BB 32
#define LL 512
#define DIN 768
#define HH 16
#define DHH 48
#define DOUTC 768
#define M_TOT (BB*LL)
#define NEGC 1e12f
#define SCALEC 0.14433756729740643f   /* 1/sqrt(48) */

// Scratch (static device globals — allowed; no runtime allocation)
__device__ float g_q[(size_t)M_TOT * DOUTC];
__device__ float g_k[(size_t)M_TOT * DOUTC];
__device__ float g_v[(size_t)M_TOT * DOUTC];

__device__ __forceinline__ unsigned packh(float lo, float hi) {
    __half2 h = __floats2half2_rn(lo, hi);
    return *(unsigned*)&h;
}

// m16n8k16 f16 with f32 accumulators
__device__ __forceinline__ void mma_f16(float* c, const unsigned* a, const unsigned* b) {
    asm volatile(
        "mma.sync.aligned.m16n8k16.row.col.f32.f16.f16.f32 "
        "{%0,%1,%2,%3}, {%4,%5,%6,%7}, {%8,%9}, {%0,%1,%2,%3};"
        : "+f"(c[0]), "+f"(c[1]), "+f"(c[2]), "+f"(c[3])
        : "r"(a[0]), "r"(a[1]), "r"(a[2]), "r"(a[3]), "r"(b[0]), "r"(b[1]));
}

// ---------------------------------------------------------------------------
// Kernel 1: FP16 tensor-core projection GEMM  Y[16384,768] = X @ W[768,768]
// 128x128 tile, K-chunk 32 (16 half2-pairs), ping-pong double buffer.
// smem layout: [pair k/2][m or n] of half2 words.
// ---------------------------------------------------------------------------
#define PADW 136
#define NCHUNK (DIN / 32)
__global__ __launch_bounds__(256, 2) void proj_gemm_tc(const float* __restrict__ X,
                                                       const float* __restrict__ W,
                                                       float* __restrict__ Y) {
    __shared__ unsigned As[2][16][PADW];   // [buf][k-pair][m]
    __shared__ unsigned Bs[2][16][PADW];   // [buf][k-pair][n]

    const int t = threadIdx.x;
    const int lane = t & 31;
    const int w = t >> 5;
    const int wm = w >> 2;
    const int wn = w & 3;
    const int g   = lane >> 2;
    const int tig = lane & 3;

    const int mBase = blockIdx.y * 128;
    const int nBase = blockIdx.x * 128;
    const int m0 = wm * 64;
    const int n0 = wn * 32;

    // A staging: row = t>>1, ahalf = t&1 selects 16 consecutive k
    const int arow = t >> 1, ahalf = t & 1;
    const float* Ap = X + (size_t)(mBase + arow) * DIN + ahalf * 16;
    // B staging: kpA = t>>5 (pair row), nq = (t&31)*4
    const int kpA = t >> 5;
    const int nq  = (lane) * 4;
    const float* Wp = W + nBase + nq;

    float acc[4][4][4];
    #pragma unroll
    for (int i = 0; i < 4; i++)
        #pragma unroll
        for (int j = 0; j < 4; j++)
            #pragma unroll
            for (int c = 0; c < 4; c++) acc[i][j][c] = 0.0f;

    float4 aV[4], bLo[2], bHi[2];
    // prefetch chunk 0
    #pragma unroll
    for (int i = 0; i < 4; i++) aV[i] = *(const float4*)(Ap + i * 4);
    #pragma unroll
    for (int p = 0; p < 2; p++) {
        const int kp = kpA + p * 8;
        bLo[p] = *(const float4*)(Wp + (size_t)(2 * kp) * DOUTC);
        bHi[p] = *(const float4*)(Wp + (size_t)(2 * kp + 1) * DOUTC);
    }
    // stage chunk 0 -> buf 0
    #pragma unroll
    for (int i = 0; i < 4; i++) {
        const int kp = ahalf * 8 + 2 * i;
        As[0][kp][arow]     = packh(aV[i].x, aV[i].y);
        As[0][kp + 1][arow] = packh(aV[i].z, aV[i].w);
    }
    #pragma unroll
    for (int p = 0; p < 2; p++) {
        const int kp = kpA + p * 8;
        *(uint4*)&Bs[0][kp][nq] = make_uint4(
            packh(bLo[p].x, bHi[p].x), packh(bLo[p].y, bHi[p].y),
            packh(bLo[p].z, bHi[p].z), packh(bLo[p].w, bHi[p].w));
    }
    __syncthreads();

    for (int c = 0; c < NCHUNK; c++) {
        const int cur = c & 1;
        const bool more = (c + 1 < NCHUNK);
        if (more) {
            const int kk = (c + 1) * 32;
            #pragma unroll
            for (int i = 0; i < 4; i++)
                aV[i] = *(const float4*)(Ap + kk + i * 4);
            #pragma unroll
            for (int p = 0; p < 2; p++) {
                const int kp = kpA + p * 8;
                bLo[p] = *(const float4*)(Wp + (size_t)(kk + 2 * kp) * DOUTC);
                bHi[p] = *(const float4*)(Wp + (size_t)(kk + 2 * kp + 1) * DOUTC);
            }
        }

        #pragma unroll
        for (int ks = 0; ks < 2; ks++) {
            const int kb = ks * 8;
            unsigned a[4][4], b[4][2];
            #pragma unroll
            for (int i = 0; i < 4; i++) {
                a[i][0] = As[cur][kb + tig    ][m0 + i * 16 + g];
                a[i][1] = As[cur][kb + tig    ][m0 + i * 16 + g + 8];
                a[i][2] = As[cur][kb + tig + 4][m0 + i * 16 + g];
                a[i][3] = As[cur][kb + tig + 4][m0 + i * 16 + g + 8];
            }
            #pragma unroll
            for (int j = 0; j < 4; j++) {
                b[j][0] = Bs[cur][kb + tig    ][n0 + j * 8 + g];
                b[j][1] = Bs[cur][kb + tig + 4][n0 + j * 8 + g];
            }
            #pragma unroll
            for (int i = 0; i < 4; i++)
                #pragma unroll
                for (int j = 0; j < 4; j++)
                    mma_f16(acc[i][j], a[i], b[j]);
        }

        if (more) {
            const int nxt = cur ^ 1;
            #pragma unroll
            for (int i = 0; i < 4; i++) {
                const int kp = ahalf * 8 + 2 * i;
                As[nxt][kp][arow]     = packh(aV[i].x, aV[i].y);
                As[nxt][kp + 1][arow] = packh(aV[i].z, aV[i].w);
            }
            #pragma unroll
            for (int p = 0; p < 2; p++) {
                const int kp = kpA + p * 8;
                *(uint4*)&Bs[nxt][kp][nq] = make_uint4(
                    packh(bLo[p].x, bHi[p].x), packh(bLo[p].y, bHi[p].y),
                    packh(bLo[p].z, bHi[p].z), packh(bLo[p].w, bHi[p].w));
            }
        }
        __syncthreads();
    }

    #pragma unroll
    for (int i = 0; i < 4; i++) {
        const size_t r1 = (size_t)(mBase + m0 + i * 16 + g);
        const size_t r2 = r1 + 8;
        #pragma unroll
        for (int j = 0; j < 4; j++) {
            const int col = nBase + n0 + j * 8 + tig * 2;
            *(float2*)(Y + r1 * DOUTC + col) = make_float2(acc[i][j][0], acc[i][j][1]);
            *(float2*)(Y + r2 * DOUTC + col) = make_float2(acc[i][j][2], acc[i][j][3]);
        }
    }
}

// ---------------------------------------------------------------------------
// Kernel 2: fused attention per (b,h), 512 threads / 16 warps, FP16 MMA.
// S^T = K·Q^T; no-max softmax; 1/l folded into V; causal tile skipping;
// register feed-forward S-frag -> O-mma A-frag (no P bounce buffer).
// smem (words are half2 where noted):
//   Kr [512][28]   K row-major, d-pairs      (57344 B)
//   Qt [24][136]   Q^T, d-pair rows x q      (13056 B)
//   Vt [48][68]    V^T, d rows x q-pairs     (13056 B)
//   sSum [16][128] per-warp partial sums     ( 8192 B)
//   lS [512]       inverse row sums          ( 2048 B)
// ---------------------------------------------------------------------------
#define KR_P 28
#define QT_P 136
#define VT_P 68
#define OFF_QT   57344
#define OFF_VT   70400
#define OFF_SSUM 83456
#define OFF_LS   91648
#define SMEM_ATT 93696

__global__ __launch_bounds__(512, 1) void attn_fused(const int* __restrict__ Qlen,
                                                     const int* __restrict__ Vlen,
                                                     float* __restrict__ Out) {
    extern __shared__ char smem[];
    unsigned* Kr   = (unsigned*)smem;
    unsigned* Qt   = (unsigned*)(smem + OFF_QT);
    unsigned* Vt   = (unsigned*)(smem + OFF_VT);
    __half*   VtH  = (__half*)(smem + OFF_VT);
    float*    sSum = (float*)(smem + OFF_SSUM);
    float*    lS   = (float*)(smem + OFF_LS);

    const int b = blockIdx.x >> 4, h = blockIdx.x & 15;
    const int t = threadIdx.x, lane = t & 31, w = t >> 5;
    const int g = lane >> 2, tig = lane & 3, w8 = w & 7;
    const int vlen = Vlen[b], qlen = Qlen[b];
    const float bias = (vlen == 0) ? NEGC : 0.0f;

    // ---- K resident: Kr[row][d-pair] ----
    for (int i = t; i < 512 * 12; i += 512) {
        const int row = i / 12, dq = (i % 12) * 4;
        float4 v = *(const float4*)&g_k[(size_t)(b * LL + row) * DOUTC + h * DHH + dq];
        *(uint2*)&Kr[row * KR_P + (dq >> 1)] =
            make_uint2(packh(v.x, v.y), packh(v.z, v.w));
    }

    // ================= PHASE A: column sums of exp(S) =================
    for (int qt = 0; qt < 4; qt++) {
        __syncthreads();
        for (int i = t; i < 128 * 12; i += 512) {
            const int row = i / 12, dq = (i % 12) * 4;
            float4 v = *(const float4*)&g_q[(size_t)(b * LL + qt * 128 + row) * DOUTC + h * DHH + dq];
            Qt[(dq >> 1) * QT_P + row]       = packh(v.x, v.y);
            Qt[((dq >> 1) + 1) * QT_P + row] = packh(v.z, v.w);
        }
        __syncthreads();

        float csum[16][2];
        #pragma unroll
        for (int nt = 0; nt < 16; nt++) { csum[nt][0] = 0.0f; csum[nt][1] = 0.0f; }
        const int kmaxc = qt * 128 + 128;

        for (int half = 0; half < 2; half++) {
            const int mr = half * 256 + w * 16;
            if (mr >= kmaxc) continue;
            const int kg0 = mr + g, kg1 = mr + g + 8;
            #pragma unroll
            for (int nb = 0; nb < 2; nb++) {
                float acc[8][4];
                #pragma unroll
                for (int nl = 0; nl < 8; nl++)
                    #pragma unroll
                    for (int c = 0; c < 4; c++) acc[nl][c] = 0.0f;
                #pragma unroll
                for (int jd = 0; jd < 24; jd += 8) {
                    unsigned a[4];
                    a[0] = Kr[(mr + g)     * KR_P + jd + tig];
                    a[1] = Kr[(mr + g + 8) * KR_P + jd + tig];
                    a[2] = Kr[(mr + g)     * KR_P + jd + tig + 4];
                    a[3] = Kr[(mr + g + 8) * KR_P + jd + tig + 4];
                    #pragma unroll
                    for (int nl = 0; nl < 8; nl++) {
                        const int n = (nb * 8 + nl) * 8 + g;
                        unsigned bf[2] = { Qt[(jd + tig) * QT_P + n],
                                           Qt[(jd + tig + 4) * QT_P + n] };
                        mma_f16(acc[nl], a, bf);
                    }
                }
                #pragma unroll
                for (int nl = 0; nl < 8; nl++) {
                    const int nt = nb * 8 + nl;
                    const int q0 = qt * 128 + nt * 8 + tig * 2;
                    float s0 = acc[nl][0] * SCALEC, s1 = acc[nl][1] * SCALEC;
                    float s2 = acc[nl][2] * SCALEC, s3 = acc[nl][3] * SCALEC;
                    if (kg0 >= vlen) { s0 -= NEGC; s1 -= NEGC; }
                    if (kg1 >= vlen) { s2 -= NEGC; s3 -= NEGC; }
                    if (kg0 > q0)     s0 -= NEGC;
                    if (kg0 > q0 + 1) s1 -= NEGC;
                    if (kg1 > q0)     s2 -= NEGC;
                    if (kg1 > q0 + 1) s3 -= NEGC;
                    csum[nt][0] += __expf(s0 + bias) + __expf(s2 + bias);
                    csum[nt][1] += __expf(s1 + bias) + __expf(s3 + bias);
                }
            }
        }
        #pragma unroll
        for (int nt = 0; nt < 16; nt++)
            #pragma unroll
            for (int p = 0; p < 2; p++) {
                float v = csum[nt][p];
                v += __shfl_xor_sync(0xffffffffu, v, 4);
                v += __shfl_xor_sync(0xffffffffu, v, 8);
                v += __shfl_xor_sync(0xffffffffu, v, 16);
                csum[nt][p] = v;
            }
        if (g == 0) {
            #pragma unroll
            for (int nt = 0; nt < 16; nt++)
                *(float2*)&sSum[w * 128 + nt * 8 + tig * 2] =
                    make_float2(csum[nt][0], csum[nt][1]);
        }
        __syncthreads();
        if (t < 128) {
            float l = 0.0f;
            #pragma unroll
            for (int w2 = 0; w2 < 16; w2++) l += sSum[w2 * 128 + t];
            lS[qt * 128 + t] = 1.0f / l;
        }
    }

    // ================= PHASE B: O = exp(S)^T · (V/l) =================
    for (int ktp = 0; ktp < 4; ktp += 2) {
        const int kt = ktp + (w >> 3);
        const int krow0 = kt * 128 + w8 * 16;
        const int kg0 = krow0 + g, kg1 = kg0 + 8;

        // K fragments: invariant across qt
        unsigned ka[3][4];
        #pragma unroll
        for (int j = 0; j < 3; j++) {
            ka[j][0] = Kr[(krow0 + g)     * KR_P + j * 8 + tig];
            ka[j][1] = Kr[(krow0 + g + 8) * KR_P + j * 8 + tig];
            ka[j][2] = Kr[(krow0 + g)     * KR_P + j * 8 + tig + 4];
            ka[j][3] = Kr[(krow0 + g + 8) * KR_P + j * 8 + tig + 4];
        }

        float oacc[6][4];
        #pragma unroll
        for (int nd = 0; nd < 6; nd++)
            #pragma unroll
            for (int c = 0; c < 4; c++) oacc[nd][c] = 0.0f;

        for (int qt = ktp; qt < 4; qt++) {
            __syncthreads();
            for (int i = t; i < 128 * 12; i += 512) {
                const int row = i / 12, dq = (i % 12) * 4;
                const size_t gof = (size_t)(b * LL + qt * 128 + row) * DOUTC + h * DHH + dq;
                float4 v = *(const float4*)&g_q[gof];
                Qt[(dq >> 1) * QT_P + row]       = packh(v.x, v.y);
                Qt[((dq >> 1) + 1) * QT_P + row] = packh(v.z, v.w);
                float4 u = *(const float4*)&g_v[gof];
                const float r = lS[qt * 128 + row];
                const int qp2 = (row >> 1) * 2 + (row & 1);   // half index within pair word
                VtH[((dq + 0) * VT_P + (row >> 1)) * 2 + (row & 1)] = __float2half(u.x * r);
                VtH[((dq + 1) * VT_P + (row >> 1)) * 2 + (row & 1)] = __float2half(u.y * r);
                VtH[((dq + 2) * VT_P + (row >> 1)) * 2 + (row & 1)] = __float2half(u.z * r);
                VtH[((dq + 3) * VT_P + (row >> 1)) * 2 + (row & 1)] = __float2half(u.w * r);
                (void)qp2;
            }
            __syncthreads();
            if (qt < kt) continue;   // fully causal-masked tile

            #pragma unroll 2
            for (int t2 = 0; t2 < 8; t2++) {
                float s4[2][4];
                #pragma unroll
                for (int hf = 0; hf < 2; hf++)
                    #pragma unroll
                    for (int c = 0; c < 4; c++) s4[hf][c] = 0.0f;
                #pragma unroll
                for (int j = 0; j < 3; j++) {
                    #pragma unroll
                    for (int hf = 0; hf < 2; hf++) {
                        const int n = (t2 * 2 + hf) * 8 + g;
                        unsigned bf[2] = { Qt[(j * 8 + tig) * QT_P + n],
                                           Qt[(j * 8 + tig + 4) * QT_P + n] };
                        mma_f16(s4[hf], ka[j], bf);
                    }
                }
                unsigned ap[4];
                #pragma unroll
                for (int hf = 0; hf < 2; hf++) {
                    const int q0 = qt * 128 + (t2 * 2 + hf) * 8 + tig * 2;
                    float s0 = s4[hf][0] * SCALEC, s1 = s4[hf][1] * SCALEC;
                    float s2 = s4[hf][2] * SCALEC, s3 = s4[hf][3] * SCALEC;
                    if (kg0 >= vlen) { s0 -= NEGC; s1 -= NEGC; }
                    if (kg1 >= vlen) { s2 -= NEGC; s3 -= NEGC; }
                    if (kg0 > q0)     s0 -= NEGC;
                    if (kg0 > q0 + 1) s1 -= NEGC;
                    if (kg1 > q0)     s2 -= NEGC;
                    if (kg1 > q0 + 1) s3 -= NEGC;
                    ap[hf * 2 + 0] = packh(__expf(s0 + bias), __expf(s1 + bias));
                    ap[hf * 2 + 1] = packh(__expf(s2 + bias), __expf(s3 + bias));
                }
                // reorder: a0,a1 = hf0 rows g/g+8; a2,a3 = hf1 rows g/g+8
                unsigned aa[4] = { ap[0], ap[1], ap[2], ap[3] };
                #pragma unroll
                for (int nd = 0; nd < 6; nd++) {
                    unsigned bf[2] = { Vt[(nd * 8 + g) * VT_P + t2 * 8 + tig],
                                       Vt[(nd * 8 + g) * VT_P + t2 * 8 + tig + 4] };
                    mma_f16(oacc[nd], aa, bf);
                }
            }
        }

        const float f0 = (kg0 < qlen) ? 1.0f : 0.0f;
        const float f1 = (kg1 < qlen) ? 1.0f : 0.0f;
        #pragma unroll
        for (int nd = 0; nd < 6; nd++) {
            const int col = h * DHH + nd * 8 + tig * 2;
            *(float2*)(Out + (size_t)(b * LL + kg0) * DOUTC + col) =
                make_float2(oacc[nd][0] * f0, oacc[nd][1] * f0);
            *(float2*)(Out + (size_t)(b * LL + kg1) * DOUTC + col) =
                make_float2(oacc[nd][2] * f1, oacc[nd][3] * f1);
        }
    }
}

// ---------------------------------------------------------------------------
extern "C" void kernel_launch(void* const* d_in, const int* in_sizes, int n_in,
                              void* d_out, int out_size) {
    const float* Qseq = (const float*)d_in[0];
    const float* Kseq = (const float*)d_in[1];
    const float* Vseq = (const float*)d_in[2];
    const float* WQ   = (const float*)d_in[3];
    const float* WK   = (const float*)d_in[4];
    const float* WV   = (const float*)d_in[5];
    const int*   Qlen = (const int*)d_in[6];
    const int*   Vlen = (const int*)d_in[7];

    float *gq, *gk, *gv;
    cudaGetSymbolAddress((void**)&gq, g_q);
    cudaGetSymbolAddress((void**)&gk, g_k);
    cudaGetSymbolAddress((void**)&gv, g_v);

    cudaFuncSetAttribute(attn_fused, cudaFuncAttributeMaxDynamicSharedMemorySize, SMEM_ATT);

    dim3 gproj(6, 128);
    proj_gemm_tc<<<gproj, 256>>>(Qseq, WQ, gq);
    proj_gemm_tc<<<gproj, 256>>>(Kseq, WK, gk);
    proj_gemm_tc<<<gproj, 256>>>(Vseq, WV, gv);

    attn_fused<<<BB * HH, 512, SMEM_ATT>>>(Qlen, Vlen, (float*)d_out);
}

// round 8
// speedup vs baseline: 5.9013x; 1.2759x over previous
#include <cuda_runtime.h>
#include <cuda_fp16.h>
#include <cstdint>

#define BB 32
#define LL 512
#define DIN 768
#define HH 16
#define DHH 48
#define DOUTC 768
#define M_TOT (BB*LL)
#define NEGC 1e12f
#define SCALEC 0.14433756729740643f   /* 1/sqrt(48) */

// fp16 scratch (static device globals)
__device__ __half g_xq16[(size_t)M_TOT * DIN];
__device__ __half g_xk16[(size_t)M_TOT * DIN];
__device__ __half g_xv16[(size_t)M_TOT * DIN];
__device__ __half g_wq16[(size_t)DIN * DOUTC];
__device__ __half g_wk16[(size_t)DIN * DOUTC];
__device__ __half g_wv16[(size_t)DIN * DOUTC];
__device__ __half g_q16[(size_t)M_TOT * DOUTC];
__device__ __half g_k16[(size_t)M_TOT * DOUTC];
__device__ __half g_v16[(size_t)M_TOT * DOUTC];

__device__ __forceinline__ unsigned packh(float lo, float hi) {
    __half2 h = __floats2half2_rn(lo, hi);
    return *(unsigned*)&h;
}

__device__ __forceinline__ void mma_f16(float* c, const unsigned* a, const unsigned* b) {
    asm volatile(
        "mma.sync.aligned.m16n8k16.row.col.f32.f16.f16.f32 "
        "{%0,%1,%2,%3}, {%4,%5,%6,%7}, {%8,%9}, {%0,%1,%2,%3};"
        : "+f"(c[0]), "+f"(c[1]), "+f"(c[2]), "+f"(c[3])
        : "r"(a[0]), "r"(a[1]), "r"(a[2]), "r"(a[3]), "r"(b[0]), "r"(b[1]));
}

__device__ __forceinline__ void ldsm4(unsigned* r, uint32_t a) {
    asm volatile("ldmatrix.sync.aligned.m8n8.x4.shared.b16 {%0,%1,%2,%3}, [%4];"
        : "=r"(r[0]), "=r"(r[1]), "=r"(r[2]), "=r"(r[3]) : "r"(a));
}
__device__ __forceinline__ void ldsm4t(unsigned* r, uint32_t a) {
    asm volatile("ldmatrix.sync.aligned.m8n8.x4.trans.shared.b16 {%0,%1,%2,%3}, [%4];"
        : "=r"(r[0]), "=r"(r[1]), "=r"(r[2]), "=r"(r[3]) : "r"(a));
}

__device__ __forceinline__ uint32_t smem_u32(const void* p) {
    uint32_t a;
    asm("{ .reg .u64 t; cvta.to.shared.u64 t, %1; cvt.u32.u64 %0, t; }"
        : "=r"(a) : "l"(p));
    return a;
}

// ---------------------------------------------------------------------------
// Prep: f32 -> f16 flat convert (3 inputs selected by blockIdx.y)
// ---------------------------------------------------------------------------
__global__ void conv_f2h(const float* __restrict__ s0, const float* __restrict__ s1,
                         const float* __restrict__ s2,
                         __half* __restrict__ d0, __half* __restrict__ d1,
                         __half* __restrict__ d2, int n4) {
    const float* s = (blockIdx.y == 0) ? s0 : (blockIdx.y == 1) ? s1 : s2;
    __half* d = (blockIdx.y == 0) ? d0 : (blockIdx.y == 1) ? d1 : d2;
    for (int i = blockIdx.x * blockDim.x + threadIdx.x; i < n4;
         i += gridDim.x * blockDim.x) {
        float4 v = ((const float4*)s)[i];
        uint2 o = make_uint2(packh(v.x, v.y), packh(v.z, v.w));
        ((uint2*)d)[i] = o;
    }
}

// ---------------------------------------------------------------------------
// Kernel 1: FP16 proj GEMM with ldmatrix.  Y16 = X16 @ W16, z selects q/k/v.
// A smem [m][k] pad 40 (non-trans LDSM); B smem [k][n] pad 136 (trans LDSM).
// ---------------------------------------------------------------------------
#define PA 40
#define PB 136
#define NCHUNK (DIN / 32)
__global__ __launch_bounds__(256, 2) void proj16(
    const __half* __restrict__ x0, const __half* __restrict__ x1,
    const __half* __restrict__ x2,
    const __half* __restrict__ w0, const __half* __restrict__ w1,
    const __half* __restrict__ w2,
    __half* __restrict__ y0, __half* __restrict__ y1, __half* __restrict__ y2) {
    const __half* X = (blockIdx.z == 0) ? x0 : (blockIdx.z == 1) ? x1 : x2;
    const __half* W = (blockIdx.z == 0) ? w0 : (blockIdx.z == 1) ? w1 : w2;
    __half* Y       = (blockIdx.z == 0) ? y0 : (blockIdx.z == 1) ? y1 : y2;

    __shared__ __align__(16) __half As[2][128 * PA];
    __shared__ __align__(16) __half Bs[2][32 * PB];

    const int t = threadIdx.x, lane = t & 31, w = t >> 5;
    const int g = lane >> 2, tig = lane & 3;
    const int m0 = (w >> 2) * 64, n0 = (w & 3) * 32;
    const int mBase = blockIdx.y * 128, nBase = blockIdx.x * 128;

    // staging coords: A row = t>>1, half = t&1 (16 halves); B krow = t>>3, n slice
    const int arow = t >> 1, ah = t & 1;
    const int brow = t >> 3, bn = (t & 7) * 16;
    const __half* Xp = X + (size_t)(mBase + arow) * DIN + ah * 16;
    const __half* Wp = W + (size_t)brow * DOUTC + nBase + bn;

    const uint32_t aBase = smem_u32(As);
    const uint32_t bBase = smem_u32(Bs);
    // per-lane LDSM half-offsets (constant parts)
    const int aLO = (lane & 15) * PA + (lane >> 4) * 8;
    const int bLO = ((lane & 7) + ((lane >> 3) & 1) * 8) * PB + (lane >> 4) * 8;

    float acc[4][4][4];
    #pragma unroll
    for (int i = 0; i < 4; i++)
        #pragma unroll
        for (int j = 0; j < 4; j++)
            #pragma unroll
            for (int c = 0; c < 4; c++) acc[i][j][c] = 0.0f;

    uint4 pA0, pA1, pB0, pB1;
    pA0 = *(const uint4*)(Xp);
    pA1 = *(const uint4*)(Xp + 8);
    pB0 = *(const uint4*)(Wp);
    pB1 = *(const uint4*)(Wp + 8);
    *(uint4*)&As[0][arow * PA + ah * 16]     = pA0;
    *(uint4*)&As[0][arow * PA + ah * 16 + 8] = pA1;
    *(uint4*)&Bs[0][brow * PB + bn]     = pB0;
    *(uint4*)&Bs[0][brow * PB + bn + 8] = pB1;
    __syncthreads();

    for (int c = 0; c < NCHUNK; c++) {
        const int cur = c & 1;
        const bool more = (c + 1 < NCHUNK);
        if (more) {
            const int kk = (c + 1) * 32;
            pA0 = *(const uint4*)(Xp + kk);
            pA1 = *(const uint4*)(Xp + kk + 8);
            pB0 = *(const uint4*)(Wp + (size_t)kk * DOUTC);
            pB1 = *(const uint4*)(Wp + (size_t)kk * DOUTC + 8);
        }

        const uint32_t aB = aBase + cur * (128 * PA * 2);
        const uint32_t bB = bBase + cur * (32 * PB * 2);
        #pragma unroll
        for (int ks = 0; ks < 2; ks++) {
            const int k0 = ks * 16;
            unsigned a[4][4];
            #pragma unroll
            for (int i = 0; i < 4; i++)
                ldsm4(a[i], aB + (uint32_t)(((m0 + i * 16) * PA) + k0 + aLO) * 2);
            #pragma unroll
            for (int jp = 0; jp < 2; jp++) {
                unsigned b4[4];
                ldsm4t(b4, bB + (uint32_t)((k0 * PB) + n0 + jp * 16 + bLO) * 2);
                #pragma unroll
                for (int i = 0; i < 4; i++) {
                    mma_f16(acc[i][jp * 2 + 0], a[i], b4);
                    mma_f16(acc[i][jp * 2 + 1], a[i], b4 + 2);
                }
            }
        }

        if (more) {
            const int nxt = cur ^ 1;
            *(uint4*)&As[nxt][arow * PA + ah * 16]     = pA0;
            *(uint4*)&As[nxt][arow * PA + ah * 16 + 8] = pA1;
            *(uint4*)&Bs[nxt][brow * PB + bn]     = pB0;
            *(uint4*)&Bs[nxt][brow * PB + bn + 8] = pB1;
        }
        __syncthreads();
    }

    #pragma unroll
    for (int i = 0; i < 4; i++) {
        const size_t r1 = (size_t)(mBase + m0 + i * 16 + g);
        const size_t r2 = r1 + 8;
        #pragma unroll
        for (int j = 0; j < 4; j++) {
            const int col = nBase + n0 + j * 8 + tig * 2;
            *(__half2*)(Y + r1 * DOUTC + col) = __floats2half2_rn(acc[i][j][0], acc[i][j][1]);
            *(__half2*)(Y + r2 * DOUTC + col) = __floats2half2_rn(acc[i][j][2], acc[i][j][3]);
        }
    }
}

// ---------------------------------------------------------------------------
// Kernel 2: fused attention per (b,h), 512 threads / 16 warps, FP16 MMA.
// Mainloop identical to R7 (validated); staging reads fp16 proj outputs.
// ---------------------------------------------------------------------------
#define KR_P 28
#define QT_P 136
#define VT_P 68
#define OFF_QT   57344
#define OFF_VT   70400
#define OFF_SSUM 83456
#define OFF_LS   91648
#define SMEM_ATT 93696

__global__ __launch_bounds__(512, 1) void attn_fused(
    const __half* __restrict__ Q16, const __half* __restrict__ K16,
    const __half* __restrict__ V16,
    const int* __restrict__ Qlen, const int* __restrict__ Vlen,
    float* __restrict__ Out) {
    extern __shared__ char smem[];
    unsigned* Kr   = (unsigned*)smem;
    unsigned* Qt   = (unsigned*)(smem + OFF_QT);
    unsigned* Vt   = (unsigned*)(smem + OFF_VT);
    __half*   VtH  = (__half*)(smem + OFF_VT);
    float*    sSum = (float*)(smem + OFF_SSUM);
    float*    lS   = (float*)(smem + OFF_LS);

    const int b = blockIdx.x >> 4, h = blockIdx.x & 15;
    const int t = threadIdx.x, lane = t & 31, w = t >> 5;
    const int g = lane >> 2, tig = lane & 3, w8 = w & 7;
    const int vlen = Vlen[b], qlen = Qlen[b];
    const float bias = (vlen == 0) ? NEGC : 0.0f;

    const __half* qsrc = Q16 + (size_t)(b * LL) * DOUTC + h * DHH;
    const __half* ksrc = K16 + (size_t)(b * LL) * DOUTC + h * DHH;
    const __half* vsrc = V16 + (size_t)(b * LL) * DOUTC + h * DHH;

    // ---- K resident: Kr[row][d-pair words], pure uint4 copies ----
    for (int i = t; i < 512 * 6; i += 512) {
        const int row = i / 6, c4 = i % 6;
        *(uint4*)&Kr[row * KR_P + c4 * 4] =
            *(const uint4*)(ksrc + (size_t)row * DOUTC + c4 * 8);
    }

    // ================= PHASE A: column sums of exp(S) =================
    for (int qt = 0; qt < 4; qt++) {
        __syncthreads();
        for (int i = t; i < 768; i += 512) {
            const int row = i / 6, c4 = i % 6;
            uint4 v = *(const uint4*)(qsrc + (size_t)(qt * 128 + row) * DOUTC + c4 * 8);
            Qt[(c4 * 4 + 0) * QT_P + row] = v.x;
            Qt[(c4 * 4 + 1) * QT_P + row] = v.y;
            Qt[(c4 * 4 + 2) * QT_P + row] = v.z;
            Qt[(c4 * 4 + 3) * QT_P + row] = v.w;
        }
        __syncthreads();

        float csum[16][2];
        #pragma unroll
        for (int nt = 0; nt < 16; nt++) { csum[nt][0] = 0.0f; csum[nt][1] = 0.0f; }
        const int kmaxc = qt * 128 + 128;

        for (int half = 0; half < 2; half++) {
            const int mr = half * 256 + w * 16;
            if (mr >= kmaxc) continue;
            const int kg0 = mr + g, kg1 = mr + g + 8;
            #pragma unroll
            for (int nb = 0; nb < 2; nb++) {
                float acc[8][4];
                #pragma unroll
                for (int nl = 0; nl < 8; nl++)
                    #pragma unroll
                    for (int c = 0; c < 4; c++) acc[nl][c] = 0.0f;
                #pragma unroll
                for (int jd = 0; jd < 24; jd += 8) {
                    unsigned a[4];
                    a[0] = Kr[(mr + g)     * KR_P + jd + tig];
                    a[1] = Kr[(mr + g + 8) * KR_P + jd + tig];
                    a[2] = Kr[(mr + g)     * KR_P + jd + tig + 4];
                    a[3] = Kr[(mr + g + 8) * KR_P + jd + tig + 4];
                    #pragma unroll
                    for (int nl = 0; nl < 8; nl++) {
                        const int n = (nb * 8 + nl) * 8 + g;
                        unsigned bf[2] = { Qt[(jd + tig) * QT_P + n],
                                           Qt[(jd + tig + 4) * QT_P + n] };
                        mma_f16(acc[nl], a, bf);
                    }
                }
                #pragma unroll
                for (int nl = 0; nl < 8; nl++) {
                    const int nt = nb * 8 + nl;
                    const int q0 = qt * 128 + nt * 8 + tig * 2;
                    float s0 = acc[nl][0] * SCALEC, s1 = acc[nl][1] * SCALEC;
                    float s2 = acc[nl][2] * SCALEC, s3 = acc[nl][3] * SCALEC;
                    if (kg0 >= vlen) { s0 -= NEGC; s1 -= NEGC; }
                    if (kg1 >= vlen) { s2 -= NEGC; s3 -= NEGC; }
                    if (kg0 > q0)     s0 -= NEGC;
                    if (kg0 > q0 + 1) s1 -= NEGC;
                    if (kg1 > q0)     s2 -= NEGC;
                    if (kg1 > q0 + 1) s3 -= NEGC;
                    csum[nt][0] += __expf(s0 + bias) + __expf(s2 + bias);
                    csum[nt][1] += __expf(s1 + bias) + __expf(s3 + bias);
                }
            }
        }
        #pragma unroll
        for (int nt = 0; nt < 16; nt++)
            #pragma unroll
            for (int p = 0; p < 2; p++) {
                float v = csum[nt][p];
                v += __shfl_xor_sync(0xffffffffu, v, 4);
                v += __shfl_xor_sync(0xffffffffu, v, 8);
                v += __shfl_xor_sync(0xffffffffu, v, 16);
                csum[nt][p] = v;
            }
        if (g == 0) {
            #pragma unroll
            for (int nt = 0; nt < 16; nt++)
                *(float2*)&sSum[w * 128 + nt * 8 + tig * 2] =
                    make_float2(csum[nt][0], csum[nt][1]);
        }
        __syncthreads();
        if (t < 128) {
            float l = 0.0f;
            #pragma unroll
            for (int w2 = 0; w2 < 16; w2++) l += sSum[w2 * 128 + t];
            lS[qt * 128 + t] = 1.0f / l;
        }
    }

    // ================= PHASE B: O = exp(S)^T · (V/l) =================
    for (int ktp = 0; ktp < 4; ktp += 2) {
        const int kt = ktp + (w >> 3);
        const int krow0 = kt * 128 + w8 * 16;
        const int kg0 = krow0 + g, kg1 = kg0 + 8;

        unsigned ka[3][4];
        #pragma unroll
        for (int j = 0; j < 3; j++) {
            ka[j][0] = Kr[(krow0 + g)     * KR_P + j * 8 + tig];
            ka[j][1] = Kr[(krow0 + g + 8) * KR_P + j * 8 + tig];
            ka[j][2] = Kr[(krow0 + g)     * KR_P + j * 8 + tig + 4];
            ka[j][3] = Kr[(krow0 + g + 8) * KR_P + j * 8 + tig + 4];
        }

        float oacc[6][4];
        #pragma unroll
        for (int nd = 0; nd < 6; nd++)
            #pragma unroll
            for (int c = 0; c < 4; c++) oacc[nd][c] = 0.0f;

        for (int qt = ktp; qt < 4; qt++) {
            __syncthreads();
            for (int i = t; i < 768; i += 512) {
                const int row = i / 6, c4 = i % 6;
                const size_t gof = (size_t)(qt * 128 + row) * DOUTC + c4 * 8;
                uint4 v = *(const uint4*)(qsrc + gof);
                Qt[(c4 * 4 + 0) * QT_P + row] = v.x;
                Qt[(c4 * 4 + 1) * QT_P + row] = v.y;
                Qt[(c4 * 4 + 2) * QT_P + row] = v.z;
                Qt[(c4 * 4 + 3) * QT_P + row] = v.w;
                uint4 u = *(const uint4*)(vsrc + gof);
                const float r = lS[qt * 128 + row];
                const __half* hp = (const __half*)&u;
                #pragma unroll
                for (int j = 0; j < 8; j++)
                    VtH[(c4 * 8 + j) * (VT_P * 2) + row] =
                        __float2half(__half2float(hp[j]) * r);
            }
            __syncthreads();
            if (qt < kt) continue;

            #pragma unroll 2
            for (int t2 = 0; t2 < 8; t2++) {
                float s4[2][4];
                #pragma unroll
                for (int hf = 0; hf < 2; hf++)
                    #pragma unroll
                    for (int c = 0; c < 4; c++) s4[hf][c] = 0.0f;
                #pragma unroll
                for (int j = 0; j < 3; j++) {
                    #pragma unroll
                    for (int hf = 0; hf < 2; hf++) {
                        const int n = (t2 * 2 + hf) * 8 + g;
                        unsigned bf[2] = { Qt[(j * 8 + tig) * QT_P + n],
                                           Qt[(j * 8 + tig + 4) * QT_P + n] };
                        mma_f16(s4[hf], ka[j], bf);
                    }
                }
                unsigned aa[4];
                #pragma unroll
                for (int hf = 0; hf < 2; hf++) {
                    const int q0 = qt * 128 + (t2 * 2 + hf) * 8 + tig * 2;
                    float s0 = s4[hf][0] * SCALEC, s1 = s4[hf][1] * SCALEC;
                    float s2 = s4[hf][2] * SCALEC, s3 = s4[hf][3] * SCALEC;
                    if (kg0 >= vlen) { s0 -= NEGC; s1 -= NEGC; }
                    if (kg1 >= vlen) { s2 -= NEGC; s3 -= NEGC; }
                    if (kg0 > q0)     s0 -= NEGC;
                    if (kg0 > q0 + 1) s1 -= NEGC;
                    if (kg1 > q0)     s2 -= NEGC;
                    if (kg1 > q0 + 1) s3 -= NEGC;
                    aa[hf * 2 + 0] = packh(__expf(s0 + bias), __expf(s1 + bias));
                    aa[hf * 2 + 1] = packh(__expf(s2 + bias), __expf(s3 + bias));
                }
                #pragma unroll
                for (int nd = 0; nd < 6; nd++) {
                    unsigned bf[2] = { Vt[(nd * 8 + g) * VT_P + t2 * 8 + tig],
                                       Vt[(nd * 8 + g) * VT_P + t2 * 8 + tig + 4] };
                    mma_f16(oacc[nd], aa, bf);
                }
            }
        }

        const float f0 = (kg0 < qlen) ? 1.0f : 0.0f;
        const float f1 = (kg1 < qlen) ? 1.0f : 0.0f;
        #pragma unroll
        for (int nd = 0; nd < 6; nd++) {
            const int col = h * DHH + nd * 8 + tig * 2;
            *(float2*)(Out + (size_t)(b * LL + kg0) * DOUTC + col) =
                make_float2(oacc[nd][0] * f0, oacc[nd][1] * f0);
            *(float2*)(Out + (size_t)(b * LL + kg1) * DOUTC + col) =
                make_float2(oacc[nd][2] * f1, oacc[nd][3] * f1);
        }
    }
}

// ---------------------------------------------------------------------------
extern "C" void kernel_launch(void* const* d_in, const int* in_sizes, int n_in,
                              void* d_out, int out_size) {
    const float* Qseq = (const float*)d_in[0];
    const float* Kseq = (const float*)d_in[1];
    const float* Vseq = (const float*)d_in[2];
    const float* WQ   = (const float*)d_in[3];
    const float* WK   = (const float*)d_in[4];
    const float* WV   = (const float*)d_in[5];
    const int*   Qlen = (const int*)d_in[6];
    const int*   Vlen = (const int*)d_in[7];

    __half *xq, *xk, *xv, *wq, *wk, *wv, *pq, *pk, *pv;
    cudaGetSymbolAddress((void**)&xq, g_xq16);
    cudaGetSymbolAddress((void**)&xk, g_xk16);
    cudaGetSymbolAddress((void**)&xv, g_xv16);
    cudaGetSymbolAddress((void**)&wq, g_wq16);
    cudaGetSymbolAddress((void**)&wk, g_wk16);
    cudaGetSymbolAddress((void**)&wv, g_wv16);
    cudaGetSymbolAddress((void**)&pq, g_q16);
    cudaGetSymbolAddress((void**)&pk, g_k16);
    cudaGetSymbolAddress((void**)&pv, g_v16);

    cudaFuncSetAttribute(attn_fused, cudaFuncAttributeMaxDynamicSharedMemorySize, SMEM_ATT);

    conv_f2h<<<dim3(2048, 3), 256>>>(Qseq, Kseq, Vseq, xq, xk, xv, M_TOT * DIN / 4);
    conv_f2h<<<dim3(576, 3), 256>>>(WQ, WK, WV, wq, wk, wv, DIN * DOUTC / 4);

    proj16<<<dim3(6, 128, 3), 256>>>(xq, xk, xv, wq, wk, wv, pq, pk, pv);

    attn_fused<<<BB * HH, 512, SMEM_ATT>>>(pq, pk, pv, Qlen, Vlen, (float*)d_out);
}

// round 9
// speedup vs baseline: 6.0964x; 1.0331x over previous
#include <cuda_runtime.h>
#include <cuda_fp16.h>
#include <cstdint>

#define BB 32
#define LL 512
#define DIN 768
#define HH 16
#define DHH 48
#define DOUTC 768
#define M_TOT (BB*LL)
#define NEGC 1e12f
#define SCALEC 0.14433756729740643f   /* 1/sqrt(48) */

// fp16 scratch (static device globals)
__device__ __half g_xq16[(size_t)M_TOT * DIN];
__device__ __half g_xk16[(size_t)M_TOT * DIN];
__device__ __half g_xv16[(size_t)M_TOT * DIN];
__device__ __half g_wq16[(size_t)DIN * DOUTC];
__device__ __half g_wk16[(size_t)DIN * DOUTC];
__device__ __half g_wv16[(size_t)DIN * DOUTC];
__device__ __half g_q16[(size_t)M_TOT * DOUTC];
__device__ __half g_k16[(size_t)M_TOT * DOUTC];
__device__ __half g_v16[(size_t)M_TOT * DOUTC];

__device__ __forceinline__ unsigned packh(float lo, float hi) {
    __half2 h = __floats2half2_rn(lo, hi);
    return *(unsigned*)&h;
}

__device__ __forceinline__ void mma_f16(float* c, const unsigned* a, const unsigned* b) {
    asm volatile(
        "mma.sync.aligned.m16n8k16.row.col.f32.f16.f16.f32 "
        "{%0,%1,%2,%3}, {%4,%5,%6,%7}, {%8,%9}, {%0,%1,%2,%3};"
        : "+f"(c[0]), "+f"(c[1]), "+f"(c[2]), "+f"(c[3])
        : "r"(a[0]), "r"(a[1]), "r"(a[2]), "r"(a[3]), "r"(b[0]), "r"(b[1]));
}

__device__ __forceinline__ void ldsm4(unsigned* r, uint32_t a) {
    asm volatile("ldmatrix.sync.aligned.m8n8.x4.shared.b16 {%0,%1,%2,%3}, [%4];"
        : "=r"(r[0]), "=r"(r[1]), "=r"(r[2]), "=r"(r[3]) : "r"(a));
}
__device__ __forceinline__ void ldsm4t(unsigned* r, uint32_t a) {
    asm volatile("ldmatrix.sync.aligned.m8n8.x4.trans.shared.b16 {%0,%1,%2,%3}, [%4];"
        : "=r"(r[0]), "=r"(r[1]), "=r"(r[2]), "=r"(r[3]) : "r"(a));
}

__device__ __forceinline__ uint32_t smem_u32(const void* p) {
    uint32_t a;
    asm("{ .reg .u64 t; cvta.to.shared.u64 t, %1; cvt.u32.u64 %0, t; }"
        : "=r"(a) : "l"(p));
    return a;
}

// ---------------------------------------------------------------------------
// Prep: f32 -> f16 flat convert (3 inputs selected by blockIdx.y)
// ---------------------------------------------------------------------------
__global__ void conv_f2h(const float* __restrict__ s0, const float* __restrict__ s1,
                         const float* __restrict__ s2,
                         __half* __restrict__ d0, __half* __restrict__ d1,
                         __half* __restrict__ d2, int n4) {
    const float* s = (blockIdx.y == 0) ? s0 : (blockIdx.y == 1) ? s1 : s2;
    __half* d = (blockIdx.y == 0) ? d0 : (blockIdx.y == 1) ? d1 : d2;
    for (int i = blockIdx.x * blockDim.x + threadIdx.x; i < n4;
         i += gridDim.x * blockDim.x) {
        float4 v = ((const float4*)s)[i];
        uint2 o = make_uint2(packh(v.x, v.y), packh(v.z, v.w));
        ((uint2*)d)[i] = o;
    }
}

// ---------------------------------------------------------------------------
// Kernel 1: FP16 proj GEMM with ldmatrix (validated R8).
// ---------------------------------------------------------------------------
#define PA 40
#define PB 136
#define NCHUNK (DIN / 32)
__global__ __launch_bounds__(256, 2) void proj16(
    const __half* __restrict__ x0, const __half* __restrict__ x1,
    const __half* __restrict__ x2,
    const __half* __restrict__ w0, const __half* __restrict__ w1,
    const __half* __restrict__ w2,
    __half* __restrict__ y0, __half* __restrict__ y1, __half* __restrict__ y2) {
    const __half* X = (blockIdx.z == 0) ? x0 : (blockIdx.z == 1) ? x1 : x2;
    const __half* W = (blockIdx.z == 0) ? w0 : (blockIdx.z == 1) ? w1 : w2;
    __half* Y       = (blockIdx.z == 0) ? y0 : (blockIdx.z == 1) ? y1 : y2;

    __shared__ __align__(16) __half As[2][128 * PA];
    __shared__ __align__(16) __half Bs[2][32 * PB];

    const int t = threadIdx.x, lane = t & 31, w = t >> 5;
    const int g = lane >> 2, tig = lane & 3;
    const int m0 = (w >> 2) * 64, n0 = (w & 3) * 32;
    const int mBase = blockIdx.y * 128, nBase = blockIdx.x * 128;

    const int arow = t >> 1, ah = t & 1;
    const int brow = t >> 3, bn = (t & 7) * 16;
    const __half* Xp = X + (size_t)(mBase + arow) * DIN + ah * 16;
    const __half* Wp = W + (size_t)brow * DOUTC + nBase + bn;

    const uint32_t aBase = smem_u32(As);
    const uint32_t bBase = smem_u32(Bs);
    const int aLO = (lane & 15) * PA + (lane >> 4) * 8;
    const int bLO = ((lane & 7) + ((lane >> 3) & 1) * 8) * PB + (lane >> 4) * 8;

    float acc[4][4][4];
    #pragma unroll
    for (int i = 0; i < 4; i++)
        #pragma unroll
        for (int j = 0; j < 4; j++)
            #pragma unroll
            for (int c = 0; c < 4; c++) acc[i][j][c] = 0.0f;

    uint4 pA0, pA1, pB0, pB1;
    pA0 = *(const uint4*)(Xp);
    pA1 = *(const uint4*)(Xp + 8);
    pB0 = *(const uint4*)(Wp);
    pB1 = *(const uint4*)(Wp + 8);
    *(uint4*)&As[0][arow * PA + ah * 16]     = pA0;
    *(uint4*)&As[0][arow * PA + ah * 16 + 8] = pA1;
    *(uint4*)&Bs[0][brow * PB + bn]     = pB0;
    *(uint4*)&Bs[0][brow * PB + bn + 8] = pB1;
    __syncthreads();

    for (int c = 0; c < NCHUNK; c++) {
        const int cur = c & 1;
        const bool more = (c + 1 < NCHUNK);
        if (more) {
            const int kk = (c + 1) * 32;
            pA0 = *(const uint4*)(Xp + kk);
            pA1 = *(const uint4*)(Xp + kk + 8);
            pB0 = *(const uint4*)(Wp + (size_t)kk * DOUTC);
            pB1 = *(const uint4*)(Wp + (size_t)kk * DOUTC + 8);
        }

        const uint32_t aB = aBase + cur * (128 * PA * 2);
        const uint32_t bB = bBase + cur * (32 * PB * 2);
        #pragma unroll
        for (int ks = 0; ks < 2; ks++) {
            const int k0 = ks * 16;
            unsigned a[4][4];
            #pragma unroll
            for (int i = 0; i < 4; i++)
                ldsm4(a[i], aB + (uint32_t)(((m0 + i * 16) * PA) + k0 + aLO) * 2);
            #pragma unroll
            for (int jp = 0; jp < 2; jp++) {
                unsigned b4[4];
                ldsm4t(b4, bB + (uint32_t)((k0 * PB) + n0 + jp * 16 + bLO) * 2);
                #pragma unroll
                for (int i = 0; i < 4; i++) {
                    mma_f16(acc[i][jp * 2 + 0], a[i], b4);
                    mma_f16(acc[i][jp * 2 + 1], a[i], b4 + 2);
                }
            }
        }

        if (more) {
            const int nxt = cur ^ 1;
            *(uint4*)&As[nxt][arow * PA + ah * 16]     = pA0;
            *(uint4*)&As[nxt][arow * PA + ah * 16 + 8] = pA1;
            *(uint4*)&Bs[nxt][brow * PB + bn]     = pB0;
            *(uint4*)&Bs[nxt][brow * PB + bn + 8] = pB1;
        }
        __syncthreads();
    }

    #pragma unroll
    for (int i = 0; i < 4; i++) {
        const size_t r1 = (size_t)(mBase + m0 + i * 16 + g);
        const size_t r2 = r1 + 8;
        #pragma unroll
        for (int j = 0; j < 4; j++) {
            const int col = nBase + n0 + j * 8 + tig * 2;
            *(__half2*)(Y + r1 * DOUTC + col) = __floats2half2_rn(acc[i][j][0], acc[i][j][1]);
            *(__half2*)(Y + r2 * DOUTC + col) = __floats2half2_rn(acc[i][j][2], acc[i][j][3]);
        }
    }
}

// ---------------------------------------------------------------------------
// Kernel 2: fused attention, R9: all fragments via ldmatrix, natural layouts.
//   Kr [512][56]h, Qs [128][56]h, Vs [128][56]h (row-major, d-contiguous)
// ---------------------------------------------------------------------------
#define RP 56                 /* row pitch in halves (48 + 8 pad) */
#define OFF_QS   57344
#define OFF_VS   71680
#define OFF_SSUM 86016
#define OFF_LS   94208
#define SMEM_ATT 96256

__global__ __launch_bounds__(512, 1) void attn_fused(
    const __half* __restrict__ Q16, const __half* __restrict__ K16,
    const __half* __restrict__ V16,
    const int* __restrict__ Qlen, const int* __restrict__ Vlen,
    float* __restrict__ Out) {
    extern __shared__ char smem[];
    __half* KrH = (__half*)smem;
    __half* QsH = (__half*)(smem + OFF_QS);
    __half* VsH = (__half*)(smem + OFF_VS);
    float*  sSum = (float*)(smem + OFF_SSUM);
    float*  lS   = (float*)(smem + OFF_LS);
    const uint32_t krB = smem_u32(smem);
    const uint32_t qsB = krB + OFF_QS;
    const uint32_t vsB = krB + OFF_VS;

    const int b = blockIdx.x >> 4, h = blockIdx.x & 15;
    const int t = threadIdx.x, lane = t & 31, w = t >> 5;
    const int g = lane >> 2, tig = lane & 3, w8 = w & 7;
    const int vlen = Vlen[b], qlen = Qlen[b];
    const float bias = (vlen == 0) ? NEGC : 0.0f;

    // lane-constant ldmatrix address parts (in halves)
    const int aSel = (lane & 15) * RP + (lane >> 4) * 8;                  // A: rows=m, contig=k
    const int bSel = ((lane & 7) + ((lane >> 4) << 3)) * RP + ((lane >> 3) & 1) * 8; // B non-trans: rows=n
    const int tSel = ((lane & 7) + (((lane >> 3) & 1) << 3)) * RP + (lane >> 4) * 8; // B trans: rows=k

    const __half* qsrc = Q16 + (size_t)(b * LL) * DOUTC + h * DHH;
    const __half* ksrc = K16 + (size_t)(b * LL) * DOUTC + h * DHH;
    const __half* vsrc = V16 + (size_t)(b * LL) * DOUTC + h * DHH;

    // ---- K resident, natural [k][d] ----
    for (int i = t; i < 3072; i += 512) {
        const int row = i / 6, c4 = i % 6;
        *(uint4*)(KrH + row * RP + c4 * 8) =
            *(const uint4*)(ksrc + (size_t)row * DOUTC + c4 * 8);
    }

    // ================= PHASE A: column sums of exp(S) =================
    for (int qt = 0; qt < 4; qt++) {
        __syncthreads();
        for (int i = t; i < 768; i += 512) {
            const int row = i / 6, c4 = i % 6;
            *(uint4*)(QsH + row * RP + c4 * 8) =
                *(const uint4*)(qsrc + (size_t)(qt * 128 + row) * DOUTC + c4 * 8);
        }
        __syncthreads();

        float csum[16][2];
        #pragma unroll
        for (int nt = 0; nt < 16; nt++) { csum[nt][0] = 0.0f; csum[nt][1] = 0.0f; }
        const int kmaxc = qt * 128 + 128;

        for (int half = 0; half < 2; half++) {
            const int mr = half * 256 + w * 16;
            if (mr >= kmaxc) continue;
            const int kg0 = mr + g, kg1 = mr + g + 8;
            unsigned a[3][4];
            #pragma unroll
            for (int jd = 0; jd < 3; jd++)
                ldsm4(a[jd], krB + (uint32_t)(mr * RP + jd * 16 + aSel) * 2);
            #pragma unroll
            for (int qg = 0; qg < 8; qg++) {
                float ac[2][4];
                #pragma unroll
                for (int s2 = 0; s2 < 2; s2++)
                    #pragma unroll
                    for (int c = 0; c < 4; c++) ac[s2][c] = 0.0f;
                #pragma unroll
                for (int jd = 0; jd < 3; jd++) {
                    unsigned b4[4];
                    ldsm4(b4, qsB + (uint32_t)(qg * 16 * RP + jd * 16 + bSel) * 2);
                    mma_f16(ac[0], a[jd], b4);
                    mma_f16(ac[1], a[jd], b4 + 2);
                }
                #pragma unroll
                for (int s2 = 0; s2 < 2; s2++) {
                    const int nt = qg * 2 + s2;
                    const int q0 = qt * 128 + nt * 8 + tig * 2;
                    float s0 = ac[s2][0] * SCALEC, s1 = ac[s2][1] * SCALEC;
                    float s2v = ac[s2][2] * SCALEC, s3 = ac[s2][3] * SCALEC;
                    if (kg0 >= vlen) { s0 -= NEGC; s1 -= NEGC; }
                    if (kg1 >= vlen) { s2v -= NEGC; s3 -= NEGC; }
                    if (kg0 > q0)     s0 -= NEGC;
                    if (kg0 > q0 + 1) s1 -= NEGC;
                    if (kg1 > q0)     s2v -= NEGC;
                    if (kg1 > q0 + 1) s3 -= NEGC;
                    csum[nt][0] += __expf(s0 + bias) + __expf(s2v + bias);
                    csum[nt][1] += __expf(s1 + bias) + __expf(s3 + bias);
                }
            }
        }
        #pragma unroll
        for (int nt = 0; nt < 16; nt++)
            #pragma unroll
            for (int p = 0; p < 2; p++) {
                float v = csum[nt][p];
                v += __shfl_xor_sync(0xffffffffu, v, 4);
                v += __shfl_xor_sync(0xffffffffu, v, 8);
                v += __shfl_xor_sync(0xffffffffu, v, 16);
                csum[nt][p] = v;
            }
        if (g == 0) {
            #pragma unroll
            for (int nt = 0; nt < 16; nt++)
                *(float2*)&sSum[w * 128 + nt * 8 + tig * 2] =
                    make_float2(csum[nt][0], csum[nt][1]);
        }
        __syncthreads();
        if (t < 128) {
            float l = 0.0f;
            #pragma unroll
            for (int w2 = 0; w2 < 16; w2++) l += sSum[w2 * 128 + t];
            lS[qt * 128 + t] = 1.0f / l;
        }
    }

    // ================= PHASE B: O = (exp(S)*r)^T · V =================
    for (int ktp = 0; ktp < 4; ktp += 2) {
        const int kt = ktp + (w >> 3);
        const int krow0 = kt * 128 + w8 * 16;
        const int kg0 = krow0 + g, kg1 = kg0 + 8;

        unsigned ka[3][4];
        #pragma unroll
        for (int jd = 0; jd < 3; jd++)
            ldsm4(ka[jd], krB + (uint32_t)(krow0 * RP + jd * 16 + aSel) * 2);

        float oacc[6][4];
        #pragma unroll
        for (int nd = 0; nd < 6; nd++)
            #pragma unroll
            for (int c = 0; c < 4; c++) oacc[nd][c] = 0.0f;

        for (int qt = ktp; qt < 4; qt++) {
            __syncthreads();
            for (int i = t; i < 768; i += 512) {
                const int row = i / 6, c4 = i % 6;
                const size_t gof = (size_t)(qt * 128 + row) * DOUTC + c4 * 8;
                *(uint4*)(QsH + row * RP + c4 * 8) = *(const uint4*)(qsrc + gof);
                *(uint4*)(VsH + row * RP + c4 * 8) = *(const uint4*)(vsrc + gof);
            }
            __syncthreads();
            if (qt < kt) continue;

            #pragma unroll 2
            for (int t2 = 0; t2 < 8; t2++) {
                float s8[2][4];
                #pragma unroll
                for (int hf = 0; hf < 2; hf++)
                    #pragma unroll
                    for (int c = 0; c < 4; c++) s8[hf][c] = 0.0f;
                #pragma unroll
                for (int jd = 0; jd < 3; jd++) {
                    unsigned b4[4];
                    ldsm4(b4, qsB + (uint32_t)(t2 * 16 * RP + jd * 16 + bSel) * 2);
                    mma_f16(s8[0], ka[jd], b4);
                    mma_f16(s8[1], ka[jd], b4 + 2);
                }
                unsigned aa[4];
                #pragma unroll
                for (int hf = 0; hf < 2; hf++) {
                    const int q0 = qt * 128 + t2 * 16 + hf * 8 + tig * 2;
                    const float2 rr = *(const float2*)&lS[q0];
                    float s0 = s8[hf][0] * SCALEC, s1 = s8[hf][1] * SCALEC;
                    float s2 = s8[hf][2] * SCALEC, s3 = s8[hf][3] * SCALEC;
                    if (kg0 >= vlen) { s0 -= NEGC; s1 -= NEGC; }
                    if (kg1 >= vlen) { s2 -= NEGC; s3 -= NEGC; }
                    if (kg0 > q0)     s0 -= NEGC;
                    if (kg0 > q0 + 1) s1 -= NEGC;
                    if (kg1 > q0)     s2 -= NEGC;
                    if (kg1 > q0 + 1) s3 -= NEGC;
                    aa[hf * 2 + 0] = packh(__expf(s0 + bias) * rr.x,
                                           __expf(s1 + bias) * rr.y);
                    aa[hf * 2 + 1] = packh(__expf(s2 + bias) * rr.x,
                                           __expf(s3 + bias) * rr.y);
                }
                #pragma unroll
                for (int dd = 0; dd < 3; dd++) {
                    unsigned b4[4];
                    ldsm4t(b4, vsB + (uint32_t)(t2 * 16 * RP + dd * 16 + tSel) * 2);
                    mma_f16(oacc[dd * 2 + 0], aa, b4);
                    mma_f16(oacc[dd * 2 + 1], aa, b4 + 2);
                }
            }
        }

        const float f0 = (kg0 < qlen) ? 1.0f : 0.0f;
        const float f1 = (kg1 < qlen) ? 1.0f : 0.0f;
        #pragma unroll
        for (int nd = 0; nd < 6; nd++) {
            const int col = h * DHH + nd * 8 + tig * 2;
            *(float2*)(Out + (size_t)(b * LL + kg0) * DOUTC + col) =
                make_float2(oacc[nd][0] * f0, oacc[nd][1] * f0);
            *(float2*)(Out + (size_t)(b * LL + kg1) * DOUTC + col) =
                make_float2(oacc[nd][2] * f1, oacc[nd][3] * f1);
        }
    }
}

// ---------------------------------------------------------------------------
extern "C" void kernel_launch(void* const* d_in, const int* in_sizes, int n_in,
                              void* d_out, int out_size) {
    const float* Qseq = (const float*)d_in[0];
    const float* Kseq = (const float*)d_in[1];
    const float* Vseq = (const float*)d_in[2];
    const float* WQ   = (const float*)d_in[3];
    const float* WK   = (const float*)d_in[4];
    const float* WV   = (const float*)d_in[5];
    const int*   Qlen = (const int*)d_in[6];
    const int*   Vlen = (const int*)d_in[7];

    __half *xq, *xk, *xv, *wq, *wk, *wv, *pq, *pk, *pv;
    cudaGetSymbolAddress((void**)&xq, g_xq16);
    cudaGetSymbolAddress((void**)&xk, g_xk16);
    cudaGetSymbolAddress((void**)&xv, g_xv16);
    cudaGetSymbolAddress((void**)&wq, g_wq16);
    cudaGetSymbolAddress((void**)&wk, g_wk16);
    cudaGetSymbolAddress((void**)&wv, g_wv16);
    cudaGetSymbolAddress((void**)&pq, g_q16);
    cudaGetSymbolAddress((void**)&pk, g_k16);
    cudaGetSymbolAddress((void**)&pv, g_v16);

    cudaFuncSetAttribute(attn_fused, cudaFuncAttributeMaxDynamicSharedMemorySize, SMEM_ATT);

    conv_f2h<<<dim3(2048, 3), 256>>>(Qseq, Kseq, Vseq, xq, xk, xv, M_TOT * DIN / 4);
    conv_f2h<<<dim3(576, 3), 256>>>(WQ, WK, WV, wq, wk, wv, DIN * DOUTC / 4);

    proj16<<<dim3(6, 128, 3), 256>>>(xq, xk, xv, wq, wk, wv, pq, pk, pv);

    attn_fused<<<BB * HH, 512, SMEM_ATT>>>(pq, pk, pv, Qlen, Vlen, (float*)d_out);
}

// round 10
// speedup vs baseline: 6.7254x; 1.1032x over previous
#include <cuda_runtime.h>
#include <cuda_fp16.h>
#include <cstdint>

#define BB 32
#define LL 512
#define DIN 768
#define HH 16
#define DHH 48
#define DOUTC 768
#define M_TOT (BB*LL)
#define NEGC 1e12f
#define SCALEC 0.14433756729740643f   /* 1/sqrt(48) */

// fp16 scratch (static device globals)
__device__ __half g_xq16[(size_t)M_TOT * DIN];
__device__ __half g_xk16[(size_t)M_TOT * DIN];
__device__ __half g_xv16[(size_t)M_TOT * DIN];
__device__ __half g_wq16[(size_t)DIN * DOUTC];
__device__ __half g_wk16[(size_t)DIN * DOUTC];
__device__ __half g_wv16[(size_t)DIN * DOUTC];
__device__ __half g_q16[(size_t)M_TOT * DOUTC];
__device__ __half g_k16[(size_t)M_TOT * DOUTC];
__device__ __half g_v16[(size_t)M_TOT * DOUTC];

__device__ __forceinline__ unsigned packh(float lo, float hi) {
    __half2 h = __floats2half2_rn(lo, hi);
    return *(unsigned*)&h;
}

__device__ __forceinline__ void mma_f16(float* c, const unsigned* a, const unsigned* b) {
    asm volatile(
        "mma.sync.aligned.m16n8k16.row.col.f32.f16.f16.f32 "
        "{%0,%1,%2,%3}, {%4,%5,%6,%7}, {%8,%9}, {%0,%1,%2,%3};"
        : "+f"(c[0]), "+f"(c[1]), "+f"(c[2]), "+f"(c[3])
        : "r"(a[0]), "r"(a[1]), "r"(a[2]), "r"(a[3]), "r"(b[0]), "r"(b[1]));
}

__device__ __forceinline__ void ldsm4(unsigned* r, uint32_t a) {
    asm volatile("ldmatrix.sync.aligned.m8n8.x4.shared.b16 {%0,%1,%2,%3}, [%4];"
        : "=r"(r[0]), "=r"(r[1]), "=r"(r[2]), "=r"(r[3]) : "r"(a));
}
__device__ __forceinline__ void ldsm4t(unsigned* r, uint32_t a) {
    asm volatile("ldmatrix.sync.aligned.m8n8.x4.trans.shared.b16 {%0,%1,%2,%3}, [%4];"
        : "=r"(r[0]), "=r"(r[1]), "=r"(r[2]), "=r"(r[3]) : "r"(a));
}

__device__ __forceinline__ uint32_t smem_u32(const void* p) {
    uint32_t a;
    asm("{ .reg .u64 t; cvta.to.shared.u64 t, %1; cvt.u32.u64 %0, t; }"
        : "=r"(a) : "l"(p));
    return a;
}

// ---------------------------------------------------------------------------
// Prep: f32 -> f16 flat convert (3 inputs selected by blockIdx.y)
// ---------------------------------------------------------------------------
__global__ void conv_f2h(const float* __restrict__ s0, const float* __restrict__ s1,
                         const float* __restrict__ s2,
                         __half* __restrict__ d0, __half* __restrict__ d1,
                         __half* __restrict__ d2, int n4) {
    const float* s = (blockIdx.y == 0) ? s0 : (blockIdx.y == 1) ? s1 : s2;
    __half* d = (blockIdx.y == 0) ? d0 : (blockIdx.y == 1) ? d1 : d2;
    for (int i = blockIdx.x * blockDim.x + threadIdx.x; i < n4;
         i += gridDim.x * blockDim.x) {
        float4 v = ((const float4*)s)[i];
        uint2 o = make_uint2(packh(v.x, v.y), packh(v.z, v.w));
        ((uint2*)d)[i] = o;
    }
}

// ---------------------------------------------------------------------------
// Kernel 1: FP16 proj GEMM with ldmatrix (validated R8).
// ---------------------------------------------------------------------------
#define PA 40
#define PB 136
#define NCHUNK (DIN / 32)
__global__ __launch_bounds__(256, 2) void proj16(
    const __half* __restrict__ x0, const __half* __restrict__ x1,
    const __half* __restrict__ x2,
    const __half* __restrict__ w0, const __half* __restrict__ w1,
    const __half* __restrict__ w2,
    __half* __restrict__ y0, __half* __restrict__ y1, __half* __restrict__ y2) {
    const __half* X = (blockIdx.z == 0) ? x0 : (blockIdx.z == 1) ? x1 : x2;
    const __half* W = (blockIdx.z == 0) ? w0 : (blockIdx.z == 1) ? w1 : w2;
    __half* Y       = (blockIdx.z == 0) ? y0 : (blockIdx.z == 1) ? y1 : y2;

    __shared__ __align__(16) __half As[2][128 * PA];
    __shared__ __align__(16) __half Bs[2][32 * PB];

    const int t = threadIdx.x, lane = t & 31, w = t >> 5;
    const int g = lane >> 2, tig = lane & 3;
    const int m0 = (w >> 2) * 64, n0 = (w & 3) * 32;
    const int mBase = blockIdx.y * 128, nBase = blockIdx.x * 128;

    const int arow = t >> 1, ah = t & 1;
    const int brow = t >> 3, bn = (t & 7) * 16;
    const __half* Xp = X + (size_t)(mBase + arow) * DIN + ah * 16;
    const __half* Wp = W + (size_t)brow * DOUTC + nBase + bn;

    const uint32_t aBase = smem_u32(As);
    const uint32_t bBase = smem_u32(Bs);
    const int aLO = (lane & 15) * PA + (lane >> 4) * 8;
    const int bLO = ((lane & 7) + ((lane >> 3) & 1) * 8) * PB + (lane >> 4) * 8;

    float acc[4][4][4];
    #pragma unroll
    for (int i = 0; i < 4; i++)
        #pragma unroll
        for (int j = 0; j < 4; j++)
            #pragma unroll
            for (int c = 0; c < 4; c++) acc[i][j][c] = 0.0f;

    uint4 pA0, pA1, pB0, pB1;
    pA0 = *(const uint4*)(Xp);
    pA1 = *(const uint4*)(Xp + 8);
    pB0 = *(const uint4*)(Wp);
    pB1 = *(const uint4*)(Wp + 8);
    *(uint4*)&As[0][arow * PA + ah * 16]     = pA0;
    *(uint4*)&As[0][arow * PA + ah * 16 + 8] = pA1;
    *(uint4*)&Bs[0][brow * PB + bn]     = pB0;
    *(uint4*)&Bs[0][brow * PB + bn + 8] = pB1;
    __syncthreads();

    for (int c = 0; c < NCHUNK; c++) {
        const int cur = c & 1;
        const bool more = (c + 1 < NCHUNK);
        if (more) {
            const int kk = (c + 1) * 32;
            pA0 = *(const uint4*)(Xp + kk);
            pA1 = *(const uint4*)(Xp + kk + 8);
            pB0 = *(const uint4*)(Wp + (size_t)kk * DOUTC);
            pB1 = *(const uint4*)(Wp + (size_t)kk * DOUTC + 8);
        }

        const uint32_t aB = aBase + cur * (128 * PA * 2);
        const uint32_t bB = bBase + cur * (32 * PB * 2);
        #pragma unroll
        for (int ks = 0; ks < 2; ks++) {
            const int k0 = ks * 16;
            unsigned a[4][4];
            #pragma unroll
            for (int i = 0; i < 4; i++)
                ldsm4(a[i], aB + (uint32_t)(((m0 + i * 16) * PA) + k0 + aLO) * 2);
            #pragma unroll
            for (int jp = 0; jp < 2; jp++) {
                unsigned b4[4];
                ldsm4t(b4, bB + (uint32_t)((k0 * PB) + n0 + jp * 16 + bLO) * 2);
                #pragma unroll
                for (int i = 0; i < 4; i++) {
                    mma_f16(acc[i][jp * 2 + 0], a[i], b4);
                    mma_f16(acc[i][jp * 2 + 1], a[i], b4 + 2);
                }
            }
        }

        if (more) {
            const int nxt = cur ^ 1;
            *(uint4*)&As[nxt][arow * PA + ah * 16]     = pA0;
            *(uint4*)&As[nxt][arow * PA + ah * 16 + 8] = pA1;
            *(uint4*)&Bs[nxt][brow * PB + bn]     = pB0;
            *(uint4*)&Bs[nxt][brow * PB + bn + 8] = pB1;
        }
        __syncthreads();
    }

    #pragma unroll
    for (int i = 0; i < 4; i++) {
        const size_t r1 = (size_t)(mBase + m0 + i * 16 + g);
        const size_t r2 = r1 + 8;
        #pragma unroll
        for (int j = 0; j < 4; j++) {
            const int col = nBase + n0 + j * 8 + tig * 2;
            *(__half2*)(Y + r1 * DOUTC + col) = __floats2half2_rn(acc[i][j][0], acc[i][j][1]);
            *(__half2*)(Y + r2 * DOUTC + col) = __floats2half2_rn(acc[i][j][2], acc[i][j][3]);
        }
    }
}

// ---------------------------------------------------------------------------
// Kernel 2: fused attention, R10: SINGLE PASS over q.
// Warp w owns k-rows [w*32, w*32+32). Per 32-q chunk: S^T mma -> exp (regs)
// -> block column-sum -> lS -> scale packed A by 1/l -> O accumulate.
// ---------------------------------------------------------------------------
#define RP 56                 /* row pitch in halves (48 + 8 pad) */
#define OFF_QS   57344
#define OFF_VS   64512
#define OFF_SSUM 71680
#define OFF_LS   73728
#define SMEM_ATT 73984

__global__ __launch_bounds__(512, 1) void attn_fused(
    const __half* __restrict__ Q16, const __half* __restrict__ K16,
    const __half* __restrict__ V16,
    const int* __restrict__ Qlen, const int* __restrict__ Vlen,
    float* __restrict__ Out) {
    extern __shared__ char smem[];
    __half* KrH = (__half*)smem;
    __half* QsH = (__half*)(smem + OFF_QS);
    __half* VsH = (__half*)(smem + OFF_VS);
    float*  sSum = (float*)(smem + OFF_SSUM);   // [16 warps][32 q]
    float*  lSc  = (float*)(smem + OFF_LS);     // [32] 1/l for current chunk
    const uint32_t krB = smem_u32(smem);
    const uint32_t qsB = krB + OFF_QS;
    const uint32_t vsB = krB + OFF_VS;

    const int b = blockIdx.x >> 4, h = blockIdx.x & 15;
    const int t = threadIdx.x, lane = t & 31, w = t >> 5;
    const int g = lane >> 2, tig = lane & 3;
    const int kr0 = w * 32;
    const int vlen = Vlen[b], qlen = Qlen[b];
    const float bias = (vlen == 0) ? NEGC : 0.0f;

    const int aSel = (lane & 15) * RP + (lane >> 4) * 8;
    const int bSel = ((lane & 7) + ((lane >> 4) << 3)) * RP + ((lane >> 3) & 1) * 8;
    const int tSel = ((lane & 7) + (((lane >> 3) & 1) << 3)) * RP + (lane >> 4) * 8;

    const __half* qsrc = Q16 + (size_t)(b * LL) * DOUTC + h * DHH;
    const __half* ksrc = K16 + (size_t)(b * LL) * DOUTC + h * DHH;
    const __half* vsrc = V16 + (size_t)(b * LL) * DOUTC + h * DHH;

    // ---- K resident, natural [k][d] ----
    for (int i = t; i < 3072; i += 512) {
        const int row = i / 6, c4 = i % 6;
        *(uint4*)(KrH + row * RP + c4 * 8) =
            *(const uint4*)(ksrc + (size_t)row * DOUTC + c4 * 8);
    }

    float oacc[2][6][4];
    #pragma unroll
    for (int mt = 0; mt < 2; mt++)
        #pragma unroll
        for (int nd = 0; nd < 6; nd++)
            #pragma unroll
            for (int c = 0; c < 4; c++) oacc[mt][nd][c] = 0.0f;

    const int kg0b = kr0 + g;           // mt=0 row bases
    for (int qt = 0; qt < 8; qt++) {
        __syncthreads();   // guard: previous O-mma finished reading Qs/Vs
        for (int i = t; i < 768; i += 512) {
            const int arr = i >= 384;
            const int j = arr ? i - 384 : i;
            const int row = j / 6, c4 = j % 6;
            const uint4 v = *(const uint4*)((arr ? vsrc : qsrc) +
                            (size_t)(qt * 64 + row) * DOUTC + c4 * 8);
            *(uint4*)((arr ? VsH : QsH) + row * RP + c4 * 8) = v;
        }
        __syncthreads();

        #pragma unroll
        for (int sub = 0; sub < 2; sub++) {
            const int qc = sub * 32;
            const int qbase = qt * 64 + qc;
            const bool live = (kr0 <= qbase + 31);   // warp has unmasked work

            float ac[2][4][4];
            float csum[4][2];
            #pragma unroll
            for (int n = 0; n < 4; n++) { csum[n][0] = 0.0f; csum[n][1] = 0.0f; }

            if (live) {
                #pragma unroll
                for (int mt = 0; mt < 2; mt++)
                    #pragma unroll
                    for (int n = 0; n < 4; n++)
                        #pragma unroll
                        for (int c = 0; c < 4; c++) ac[mt][n][c] = 0.0f;
                #pragma unroll
                for (int jd = 0; jd < 3; jd++) {
                    unsigned a0[4], a1[4];
                    ldsm4(a0, krB + (uint32_t)(kr0 * RP + jd * 16 + aSel) * 2);
                    ldsm4(a1, krB + (uint32_t)((kr0 + 16) * RP + jd * 16 + aSel) * 2);
                    #pragma unroll
                    for (int qg = 0; qg < 2; qg++) {
                        unsigned b4[4];
                        ldsm4(b4, qsB + (uint32_t)((qc + qg * 16) * RP + jd * 16 + bSel) * 2);
                        mma_f16(ac[0][qg * 2 + 0], a0, b4);
                        mma_f16(ac[0][qg * 2 + 1], a0, b4 + 2);
                        mma_f16(ac[1][qg * 2 + 0], a1, b4);
                        mma_f16(ac[1][qg * 2 + 1], a1, b4 + 2);
                    }
                }
                // mask + exp in place + column sums
                #pragma unroll
                for (int mt = 0; mt < 2; mt++) {
                    const int kg0 = kg0b + mt * 16, kg1 = kg0 + 8;
                    #pragma unroll
                    for (int n = 0; n < 4; n++) {
                        const int q0 = qbase + n * 8 + tig * 2;
                        float s0 = ac[mt][n][0] * SCALEC, s1 = ac[mt][n][1] * SCALEC;
                        float s2 = ac[mt][n][2] * SCALEC, s3 = ac[mt][n][3] * SCALEC;
                        if (kg0 >= vlen) { s0 -= NEGC; s1 -= NEGC; }
                        if (kg1 >= vlen) { s2 -= NEGC; s3 -= NEGC; }
                        if (kg0 > q0)     s0 -= NEGC;
                        if (kg0 > q0 + 1) s1 -= NEGC;
                        if (kg1 > q0)     s2 -= NEGC;
                        if (kg1 > q0 + 1) s3 -= NEGC;
                        const float e0 = __expf(s0 + bias), e1 = __expf(s1 + bias);
                        const float e2 = __expf(s2 + bias), e3 = __expf(s3 + bias);
                        ac[mt][n][0] = e0; ac[mt][n][1] = e1;
                        ac[mt][n][2] = e2; ac[mt][n][3] = e3;
                        csum[n][0] += e0 + e2;
                        csum[n][1] += e1 + e3;
                    }
                }
            }
            // reduce over rows (g lanes) and write per-warp partials
            #pragma unroll
            for (int n = 0; n < 4; n++)
                #pragma unroll
                for (int p = 0; p < 2; p++) {
                    float v = csum[n][p];
                    v += __shfl_xor_sync(0xffffffffu, v, 4);
                    v += __shfl_xor_sync(0xffffffffu, v, 8);
                    v += __shfl_xor_sync(0xffffffffu, v, 16);
                    csum[n][p] = v;
                }
            if (g == 0) {
                #pragma unroll
                for (int n = 0; n < 4; n++)
                    *(float2*)&sSum[w * 32 + n * 8 + tig * 2] =
                        make_float2(csum[n][0], csum[n][1]);
            }
            __syncthreads();
            if (t < 32) {
                float l = 0.0f;
                #pragma unroll
                for (int w2 = 0; w2 < 16; w2++) l += sSum[w2 * 32 + t];
                lSc[t] = 1.0f / l;
            }
            __syncthreads();

            if (live) {
                #pragma unroll
                for (int kc = 0; kc < 2; kc++) {
                    const float2 rrA = *(const float2*)&lSc[kc * 16 + tig * 2];
                    const float2 rrB = *(const float2*)&lSc[kc * 16 + 8 + tig * 2];
                    unsigned aa[2][4];
                    #pragma unroll
                    for (int mt = 0; mt < 2; mt++) {
                        aa[mt][0] = packh(ac[mt][kc * 2][0] * rrA.x, ac[mt][kc * 2][1] * rrA.y);
                        aa[mt][1] = packh(ac[mt][kc * 2][2] * rrA.x, ac[mt][kc * 2][3] * rrA.y);
                        aa[mt][2] = packh(ac[mt][kc * 2 + 1][0] * rrB.x, ac[mt][kc * 2 + 1][1] * rrB.y);
                        aa[mt][3] = packh(ac[mt][kc * 2 + 1][2] * rrB.x, ac[mt][kc * 2 + 1][3] * rrB.y);
                    }
                    #pragma unroll
                    for (int dd = 0; dd < 3; dd++) {
                        unsigned b4[4];
                        ldsm4t(b4, vsB + (uint32_t)((qc + kc * 16) * RP + dd * 16 + tSel) * 2);
                        mma_f16(oacc[0][dd * 2 + 0], aa[0], b4);
                        mma_f16(oacc[0][dd * 2 + 1], aa[0], b4 + 2);
                        mma_f16(oacc[1][dd * 2 + 0], aa[1], b4);
                        mma_f16(oacc[1][dd * 2 + 1], aa[1], b4 + 2);
                    }
                }
            }
        }
    }

    // epilogue
    #pragma unroll
    for (int mt = 0; mt < 2; mt++) {
        const int kg0 = kr0 + mt * 16 + g, kg1 = kg0 + 8;
        const float f0 = (kg0 < qlen) ? 1.0f : 0.0f;
        const float f1 = (kg1 < qlen) ? 1.0f : 0.0f;
        #pragma unroll
        for (int nd = 0; nd < 6; nd++) {
            const int col = h * DHH + nd * 8 + tig * 2;
            *(float2*)(Out + (size_t)(b * LL + kg0) * DOUTC + col) =
                make_float2(oacc[mt][nd][0] * f0, oacc[mt][nd][1] * f0);
            *(float2*)(Out + (size_t)(b * LL + kg1) * DOUTC + col) =
                make_float2(oacc[mt][nd][2] * f1, oacc[mt][nd][3] * f1);
        }
    }
}

// ---------------------------------------------------------------------------
extern "C" void kernel_launch(void* const* d_in, const int* in_sizes, int n_in,
                              void* d_out, int out_size) {
    const float* Qseq = (const float*)d_in[0];
    const float* Kseq = (const float*)d_in[1];
    const float* Vseq = (const float*)d_in[2];
    const float* WQ   = (const float*)d_in[3];
    const float* WK   = (const float*)d_in[4];
    const float* WV   = (const float*)d_in[5];
    const int*   Qlen = (const int*)d_in[6];
    const int*   Vlen = (const int*)d_in[7];

    __half *xq, *xk, *xv, *wq, *wk, *wv, *pq, *pk, *pv;
    cudaGetSymbolAddress((void**)&xq, g_xq16);
    cudaGetSymbolAddress((void**)&xk, g_xk16);
    cudaGetSymbolAddress((void**)&xv, g_xv16);
    cudaGetSymbolAddress((void**)&wq, g_wq16);
    cudaGetSymbolAddress((void**)&wk, g_wk16);
    cudaGetSymbolAddress((void**)&wv, g_wv16);
    cudaGetSymbolAddress((void**)&pq, g_q16);
    cudaGetSymbolAddress((void**)&pk, g_k16);
    cudaGetSymbolAddress((void**)&pv, g_v16);

    cudaFuncSetAttribute(attn_fused, cudaFuncAttributeMaxDynamicSharedMemorySize, SMEM_ATT);

    conv_f2h<<<dim3(2048, 3), 256>>>(Qseq, Kseq, Vseq, xq, xk, xv, M_TOT * DIN / 4);
    conv_f2h<<<dim3(576, 3), 256>>>(WQ, WK, WV, wq, wk, wv, DIN * DOUTC / 4);

    proj16<<<dim3(6, 128, 3), 256>>>(xq, xk, xv, wq, wk, wv, pq, pk, pv);

    attn_fused<<<BB * HH, 512, SMEM_ATT>>>(pq, pk, pv, Qlen, Vlen, (float*)d_out);
}